// round 3
// baseline (speedup 1.0000x reference)
#include <cuda_runtime.h>
#include <mma.h>
#include <cstdint>

using namespace nvcuda;

#define B_  4
#define S_  2048
#define D_  1024
#define H_  16
#define DH  64

// Scratch (device globals -- no allocations allowed)
__device__ float g_q[(size_t)B_*H_*S_*DH];     // 33.5 MB
__device__ float g_k[(size_t)B_*H_*S_*DH];     // 33.5 MB
__device__ float g_ksum[B_*H_*DH];

// ---------------------------------------------------------------------------
// Kernel 1: fused q/k projection with wmma tf32 (3xTF32 split for fp32-class
// accuracy).  C[m,n] = x[m,:] . W[n,:] + bias[n].  M=8192 N=2048 K=1024.
// CTA tile 128x128, 8 warps (2m x 4n), warp tile 64x32, K-chunk 16, double buf.
// ---------------------------------------------------------------------------
#define PJ_KC   16
#define PJ_LDS  20                      // stage stride (floats)
#define PJ_STG  (128 * PJ_LDS)          // floats per array per stage (2560)
#define PJ_LDC  132                     // epilogue C stride
#define PJ_SMEM_BYTES (2 * 4 * PJ_STG * 4)   // 81920 (>= 128*132*4 epilogue)

__global__ __launch_bounds__(256) void proj_wmma_kernel(
    const float* __restrict__ x, const float* __restrict__ W,
    const float* __restrict__ bias)
{
    extern __shared__ float sm[];
    // stage layout: [stage][Ah, Al, Bh, Bl], each 128 x PJ_LDS
    float* Ah[2] = { sm,              sm + 4 * PJ_STG };
    float* Al[2] = { Ah[0] + PJ_STG,  Ah[1] + PJ_STG };
    float* Bh[2] = { Al[0] + PJ_STG,  Al[1] + PJ_STG };
    float* Bl[2] = { Bh[0] + PJ_STG,  Bh[1] + PJ_STG };

    __shared__ float sBias[128];

    const int tid = threadIdx.x;
    const int m0 = blockIdx.y * 128;
    const int n0 = blockIdx.x * 128;
    const int wid = tid >> 5;
    const int wm = wid & 1;            // m strip (0..1) of 64
    const int wn = wid >> 1;           // n strip (0..3) of 32

    if (tid < 128) sBias[tid] = bias[n0 + tid];

    const int lrow = tid & 127;
    const int lseg = (tid >> 7) * 8;   // 0 or 8

    const float* aptr = x + (size_t)(m0 + lrow) * D_ + lseg;
    const float* bptr = W + (size_t)(n0 + lrow) * D_ + lseg;

    wmma::fragment<wmma::accumulator, 16, 16, 8, float> acc[4][2];
#pragma unroll
    for (int i = 0; i < 4; i++)
#pragma unroll
        for (int j = 0; j < 2; j++) wmma::fill_fragment(acc[i][j], 0.f);

    float4 ra0, ra1, rb0, rb1;
    auto load_regs = [&](int kc) {
        const float* ap = aptr + kc * PJ_KC;
        const float* bp = bptr + kc * PJ_KC;
        ra0 = *(const float4*)(ap);
        ra1 = *(const float4*)(ap + 4);
        rb0 = *(const float4*)(bp);
        rb1 = *(const float4*)(bp + 4);
    };
    auto split_store = [&](int buf) {
        float av[8] = { ra0.x, ra0.y, ra0.z, ra0.w, ra1.x, ra1.y, ra1.z, ra1.w };
        float bv[8] = { rb0.x, rb0.y, rb0.z, rb0.w, rb1.x, rb1.y, rb1.z, rb1.w };
        float* ah = Ah[buf] + lrow * PJ_LDS + lseg;
        float* al = Al[buf] + lrow * PJ_LDS + lseg;
        float* bh = Bh[buf] + lrow * PJ_LDS + lseg;
        float* bl = Bl[buf] + lrow * PJ_LDS + lseg;
#pragma unroll
        for (int i = 0; i < 8; i++) {
            float hi = wmma::__float_to_tf32(av[i]);
            ah[i] = hi;
            al[i] = wmma::__float_to_tf32(av[i] - hi);
            float bhi = wmma::__float_to_tf32(bv[i]);
            bh[i] = bhi;
            bl[i] = wmma::__float_to_tf32(bv[i] - bhi);
        }
    };

    load_regs(0);
    split_store(0);
    __syncthreads();

    const int NKC = D_ / PJ_KC;        // 64
    for (int kc = 0; kc < NKC; kc++) {
        const int buf = kc & 1;
        if (kc < NKC - 1) load_regs(kc + 1);

        // compute on buf
#pragma unroll
        for (int ks = 0; ks < PJ_KC; ks += 8) {
            wmma::fragment<wmma::matrix_a, 16, 16, 8, wmma::precision::tf32, wmma::row_major> ah_f[4], al_f[4];
            wmma::fragment<wmma::matrix_b, 16, 16, 8, wmma::precision::tf32, wmma::col_major> bh_f[2], bl_f[2];
#pragma unroll
            for (int i = 0; i < 4; i++) {
                wmma::load_matrix_sync(ah_f[i], Ah[buf] + (wm * 64 + i * 16) * PJ_LDS + ks, PJ_LDS);
                wmma::load_matrix_sync(al_f[i], Al[buf] + (wm * 64 + i * 16) * PJ_LDS + ks, PJ_LDS);
            }
#pragma unroll
            for (int j = 0; j < 2; j++) {
                wmma::load_matrix_sync(bh_f[j], Bh[buf] + (wn * 32 + j * 16) * PJ_LDS + ks, PJ_LDS);
                wmma::load_matrix_sync(bl_f[j], Bl[buf] + (wn * 32 + j * 16) * PJ_LDS + ks, PJ_LDS);
            }
#pragma unroll
            for (int i = 0; i < 4; i++)
#pragma unroll
                for (int j = 0; j < 2; j++) {
                    wmma::mma_sync(acc[i][j], ah_f[i], bl_f[j], acc[i][j]);
                    wmma::mma_sync(acc[i][j], al_f[i], bh_f[j], acc[i][j]);
                    wmma::mma_sync(acc[i][j], ah_f[i], bh_f[j], acc[i][j]);
                }
        }
        __syncthreads();
        if (kc < NKC - 1) {
            split_store(buf ^ 1);
            __syncthreads();
        }
    }

    // ---- epilogue: frags -> smem C -> scatter to g_q / g_k ----
    float* Cs = sm;                    // 128 x PJ_LDC
#pragma unroll
    for (int i = 0; i < 4; i++)
#pragma unroll
        for (int j = 0; j < 2; j++)
            wmma::store_matrix_sync(Cs + (wm * 64 + i * 16) * PJ_LDC + wn * 32 + j * 16,
                                    acc[i][j], PJ_LDC, wmma::mem_row_major);
    __syncthreads();

    {
        const int r    = tid >> 1;
        const int half = tid & 1;
        const int m = m0 + r;
        const int bb = m >> 11;
        const int s_idx = m & 2047;
        const int hh = n0 >> 7;        // PTC_N == 128 -> single head column
        const size_t base = (((size_t)bb * H_ + hh) * S_ + s_idx) * DH + half * 32;
        float qv[32], kv[32];
#pragma unroll
        for (int jj = 0; jj < 32; jj++) {
            const int j = half * 64 + 2 * jj;
            qv[jj] = Cs[r * PJ_LDC + j]     + sBias[j];
            kv[jj] = Cs[r * PJ_LDC + j + 1] + sBias[j + 1];
        }
#pragma unroll
        for (int v = 0; v < 8; v++) {
            *(float4*)(g_q + base + v * 4) =
                make_float4(qv[v*4+0], qv[v*4+1], qv[v*4+2], qv[v*4+3]);
            *(float4*)(g_k + base + v * 4) =
                make_float4(kv[v*4+0], kv[v*4+1], kv[v*4+2], kv[v*4+3]);
        }
    }
}

// ---------------------------------------------------------------------------
// Kernel 2: ksum[b,h,d] = sum_s k[b,h,s,d]
// ---------------------------------------------------------------------------
__global__ __launch_bounds__(256) void ksum_kernel()
{
    __shared__ float red[256];
    const int bh = blockIdx.x;
    const int t = threadIdx.x;
    const int d = t & 63;
    const int chunk = t >> 6;
    const float* base = g_k + (size_t)bh * S_ * DH;
    float s = 0.f;
    const int j0 = chunk * (S_ / 4), j1 = j0 + (S_ / 4);
    for (int j = j0; j < j1; j++) s += base[(size_t)j * DH + d];
    red[t] = s;
    __syncthreads();
    if (t < 64)
        g_ksum[bh * DH + t] = red[t] + red[64 + t] + red[128 + t] + red[192 + t];
}

// ---------------------------------------------------------------------------
// Kernel 3: fused attention with wmma tf32.  Per (b, h, 128 q-rows):
//   mean_i = (scale/S) q_i . ksum ;  P = QK^T ; A = selu(P*scale - mean)
//   out = A @ V * S^-0.5,  V read directly from x.
// smem (floats): qs[128][68], ks[128][68], vs[128][68], ps[128][132]
// ---------------------------------------------------------------------------
#define AT_LDQ 68
#define AT_LDP 132
#define AT_QS  0
#define AT_KS  (128 * AT_LDQ)
#define AT_VS  (2 * 128 * AT_LDQ)
#define AT_PS  (3 * 128 * AT_LDQ)
#define AT_SMEM_BYTES ((3 * 128 * AT_LDQ + 128 * AT_LDP) * 4)   // 172032

__global__ __launch_bounds__(256) void attn_wmma_kernel(
    const float* __restrict__ x, float* __restrict__ out)
{
    extern __shared__ float sm[];
    float* qs = sm + AT_QS;
    float* ks = sm + AT_KS;
    float* vs = sm + AT_VS;
    float* ps = sm + AT_PS;
    __shared__ float sKsum[64];
    __shared__ float sMrow[128];

    const int b  = blockIdx.z;
    const int h  = blockIdx.y;
    const int s0 = blockIdx.x * 128;
    const int tid = threadIdx.x;
    const int wid = tid >> 5;

    const size_t bh = (size_t)b * H_ + h;
    const float* qg = g_q + bh * S_ * DH;
    const float* kg = g_k + bh * S_ * DH;

    const int lrow = tid >> 1;
    const int lseg = (tid & 1) * 32;

    // ---- load Q tile (tf32-rounded) ----
    {
        const float* src = qg + (size_t)(s0 + lrow) * DH + lseg;
        float* dst = qs + lrow * AT_LDQ + lseg;
#pragma unroll
        for (int v = 0; v < 8; v++) {
            float4 q4 = *(const float4*)(src + v * 4);
            dst[v*4+0] = wmma::__float_to_tf32(q4.x);
            dst[v*4+1] = wmma::__float_to_tf32(q4.y);
            dst[v*4+2] = wmma::__float_to_tf32(q4.z);
            dst[v*4+3] = wmma::__float_to_tf32(q4.w);
        }
    }
    if (tid < 64) sKsum[tid] = g_ksum[bh * DH + tid];
    __syncthreads();

    const float SCALE = 0.125f;
    if (tid < 128) {
        float s = 0.f;
        const float* qr = qs + tid * AT_LDQ;
#pragma unroll
        for (int d = 0; d < DH; d++) s += qr[d] * sKsum[d];
        sMrow[tid] = s * (SCALE / (float)S_);
    }
    __syncthreads();

    // persistent output accumulators: warp (wid>>1) = m strip of 32,
    // (wid&1) = n strip of 32; 2x2 frags of 16x16.
    const int wmA = wid >> 1;
    const int wnA = wid & 1;
    wmma::fragment<wmma::accumulator, 16, 16, 8, float> oacc[2][2];
#pragma unroll
    for (int i = 0; i < 2; i++)
#pragma unroll
        for (int j = 0; j < 2; j++) wmma::fill_fragment(oacc[i][j], 0.f);

    // QK warp mapping: (wid&1) = m strip of 64, (wid>>1) = n strip of 32
    const int wmQ = wid & 1;
    const int wnQ = wid >> 1;

    for (int j0 = 0; j0 < S_; j0 += 128) {
        __syncthreads();   // prev iter's AV reads of ks/vs done

        // ---- load K tile + V tile (tf32-rounded) ----
        {
            const float* ksrc = kg + (size_t)(j0 + lrow) * DH + lseg;
            const float* vsrc = x + ((size_t)b * S_ + j0 + lrow) * D_ + h * DH + lseg;
            float* kdst = ks + lrow * AT_LDQ + lseg;
            float* vdst = vs + lrow * AT_LDQ + lseg;
#pragma unroll
            for (int v = 0; v < 8; v++) {
                float4 k4 = *(const float4*)(ksrc + v * 4);
                kdst[v*4+0] = wmma::__float_to_tf32(k4.x);
                kdst[v*4+1] = wmma::__float_to_tf32(k4.y);
                kdst[v*4+2] = wmma::__float_to_tf32(k4.z);
                kdst[v*4+3] = wmma::__float_to_tf32(k4.w);
                float4 v4 = *(const float4*)(vsrc + v * 4);
                vdst[v*4+0] = wmma::__float_to_tf32(v4.x);
                vdst[v*4+1] = wmma::__float_to_tf32(v4.y);
                vdst[v*4+2] = wmma::__float_to_tf32(v4.z);
                vdst[v*4+3] = wmma::__float_to_tf32(v4.w);
            }
        }
        __syncthreads();

        // ---- P = Q K^T ----
        {
            wmma::fragment<wmma::accumulator, 16, 16, 8, float> pacc[4][2];
#pragma unroll
            for (int i = 0; i < 4; i++)
#pragma unroll
                for (int j = 0; j < 2; j++) wmma::fill_fragment(pacc[i][j], 0.f);

#pragma unroll
            for (int kd = 0; kd < DH; kd += 8) {
                wmma::fragment<wmma::matrix_a, 16, 16, 8, wmma::precision::tf32, wmma::row_major> af[4];
                wmma::fragment<wmma::matrix_b, 16, 16, 8, wmma::precision::tf32, wmma::col_major> bf[2];
#pragma unroll
                for (int i = 0; i < 4; i++)
                    wmma::load_matrix_sync(af[i], qs + (wmQ * 64 + i * 16) * AT_LDQ + kd, AT_LDQ);
#pragma unroll
                for (int j = 0; j < 2; j++)
                    wmma::load_matrix_sync(bf[j], ks + (wnQ * 32 + j * 16) * AT_LDQ + kd, AT_LDQ);
#pragma unroll
                for (int i = 0; i < 4; i++)
#pragma unroll
                    for (int j = 0; j < 2; j++)
                        wmma::mma_sync(pacc[i][j], af[i], bf[j], pacc[i][j]);
            }
#pragma unroll
            for (int i = 0; i < 4; i++)
#pragma unroll
                for (int j = 0; j < 2; j++)
                    wmma::store_matrix_sync(ps + (wmQ * 64 + i * 16) * AT_LDP + wnQ * 32 + j * 16,
                                            pacc[i][j], AT_LDP, wmma::mem_row_major);
        }
        __syncthreads();

        // ---- selu(P*scale - mean), tf32-rounded, in place ----
        {
            const int r = tid >> 1;
            const int cb = (tid & 1) * 64;
            const float mr = sMrow[r];
            float* pr = ps + r * AT_LDP + cb;
#pragma unroll 8
            for (int c = 0; c < 64; c++) {
                const float s = pr[c] * SCALE - mr;
                const float r_ = (s > 0.f)
                    ? 1.0507009873554805f * s
                    : 1.7580993408473766f * (__expf(s) - 1.f);
                pr[c] = wmma::__float_to_tf32(r_);
            }
        }
        __syncthreads();

        // ---- oacc += A @ V ----
        {
#pragma unroll
            for (int kj = 0; kj < 128; kj += 8) {
                wmma::fragment<wmma::matrix_a, 16, 16, 8, wmma::precision::tf32, wmma::row_major> af[2];
                wmma::fragment<wmma::matrix_b, 16, 16, 8, wmma::precision::tf32, wmma::row_major> bf[2];
#pragma unroll
                for (int i = 0; i < 2; i++)
                    wmma::load_matrix_sync(af[i], ps + (wmA * 32 + i * 16) * AT_LDP + kj, AT_LDP);
#pragma unroll
                for (int j = 0; j < 2; j++)
                    wmma::load_matrix_sync(bf[j], vs + kj * AT_LDQ + wnA * 32 + j * 16, AT_LDQ);
#pragma unroll
                for (int i = 0; i < 2; i++)
#pragma unroll
                    for (int j = 0; j < 2; j++)
                        wmma::mma_sync(oacc[i][j], af[i], bf[j], oacc[i][j]);
            }
        }
    }
    __syncthreads();

    // ---- epilogue: oacc -> ps -> gmem ----
#pragma unroll
    for (int i = 0; i < 2; i++)
#pragma unroll
        for (int j = 0; j < 2; j++)
            wmma::store_matrix_sync(ps + (wmA * 32 + i * 16) * AT_LDP + wnA * 32 + j * 16,
                                    oacc[i][j], AT_LDP, wmma::mem_row_major);
    __syncthreads();

    {
        const float OS = 0.022097086912079608f;    // 2048^-0.5
        const int r = tid >> 1;
        const int seg = (tid & 1) * 32;
        const float* pr = ps + r * AT_LDP + seg;
        float* dst = out + ((size_t)b * S_ + s0 + r) * D_ + h * DH + seg;
#pragma unroll
        for (int v = 0; v < 8; v++) {
            float4 o4 = make_float4(pr[v*4+0] * OS, pr[v*4+1] * OS,
                                    pr[v*4+2] * OS, pr[v*4+3] * OS);
            *(float4*)(dst + v * 4) = o4;
        }
    }
}

// ---------------------------------------------------------------------------
extern "C" void kernel_launch(void* const* d_in, const int* in_sizes, int n_in,
                              void* d_out, int out_size)
{
    const float* x    = (const float*)d_in[0];
    const float* W    = (const float*)d_in[1];
    const float* bias = (const float*)d_in[2];
    float* out = (float*)d_out;

    cudaFuncSetAttribute(proj_wmma_kernel,
                         cudaFuncAttributeMaxDynamicSharedMemorySize, PJ_SMEM_BYTES);
    cudaFuncSetAttribute(attn_wmma_kernel,
                         cudaFuncAttributeMaxDynamicSharedMemorySize, AT_SMEM_BYTES);

    dim3 pg(D_ * 2 / 128, (B_ * S_) / 128);          // (16, 64)
    proj_wmma_kernel<<<pg, 256, PJ_SMEM_BYTES>>>(x, W, bias);

    ksum_kernel<<<B_ * H_, 256>>>();

    dim3 ag(S_ / 128, H_, B_);                       // (16, 16, 4)
    attn_wmma_kernel<<<ag, 256, AT_SMEM_BYTES>>>(x, out);
}

// round 4
// speedup vs baseline: 1.9561x; 1.9561x over previous
#include <cuda_runtime.h>
#include <mma.h>
#include <cstdint>

using namespace nvcuda;

#define B_  4
#define S_  2048
#define D_  1024
#define H_  16
#define DH  64

// Scratch (device globals -- no allocations allowed)
__device__ float g_q[(size_t)B_*H_*S_*DH];       // 33.5 MB (tf32-rounded q)
__device__ float g_k[(size_t)B_*H_*S_*DH];       // 33.5 MB (tf32-rounded k)
__device__ float g_xc[(size_t)B_*S_*D_];         // 33.5 MB (tf32-rounded x)
__device__ float g_wc[(size_t)2*D_*D_];          // 8.4 MB  (tf32-rounded W)
__device__ float g_ksum[B_*H_*DH];

// ---------------------------------------------------------------------------
// helpers
// ---------------------------------------------------------------------------
__device__ __forceinline__ uint32_t smem_u32(const void* p) {
    uint32_t a;
    asm("{ .reg .u64 t; cvta.to.shared.u64 t, %1; cvt.u32.u64 %0, t; }"
        : "=r"(a) : "l"(p));
    return a;
}
#define CP_ASYNC16(dst, src) \
    asm volatile("cp.async.cg.shared.global [%0], [%1], 16;" :: "r"(dst), "l"(src) : "memory")
#define CP_COMMIT() asm volatile("cp.async.commit_group;" ::: "memory")
#define CP_WAIT(N)  asm volatile("cp.async.wait_group %0;" :: "n"(N) : "memory")

// ---------------------------------------------------------------------------
// Kernel 0: tf32-round x and W into scratch (hoists all cvt out of hot loops)
// ---------------------------------------------------------------------------
#define XC_F4 ((size_t)B_*S_*D_/4)       // 2097152
#define WC_F4 ((size_t)2*D_*D_/4)        // 524288

__global__ __launch_bounds__(256) void cvt_kernel(
    const float* __restrict__ x, const float* __restrict__ W)
{
    const size_t i = (size_t)blockIdx.x * 256 + threadIdx.x;
    if (i < XC_F4) {
        float4 v = ((const float4*)x)[i];
        v.x = wmma::__float_to_tf32(v.x); v.y = wmma::__float_to_tf32(v.y);
        v.z = wmma::__float_to_tf32(v.z); v.w = wmma::__float_to_tf32(v.w);
        ((float4*)g_xc)[i] = v;
    } else if (i < XC_F4 + WC_F4) {
        const size_t j = i - XC_F4;
        float4 v = ((const float4*)W)[j];
        v.x = wmma::__float_to_tf32(v.x); v.y = wmma::__float_to_tf32(v.y);
        v.z = wmma::__float_to_tf32(v.z); v.w = wmma::__float_to_tf32(v.w);
        ((float4*)g_wc)[j] = v;
    }
}

// ---------------------------------------------------------------------------
// Kernel 1: fused q/k projection, plain tf32 wmma.
// C[m,n] = xc[m,:].Wc[n,:] + bias[n].  M=8192 N=2048 K=1024.
// CTA 128x128, 8 warps (2m x 4n -> warp 64x32), K-chunk 32, 2-stage cp.async.
// Epilogue scatters tf32-rounded q/k.
// ---------------------------------------------------------------------------
#define PJ_LD   36
#define PJ_STGF (2 * 128 * PJ_LD)            // floats per stage (A+B) = 9216
#define PJ_SMEM (2 * PJ_STGF * 4)            // 73728 B
#define PJ_LDC  132

__global__ __launch_bounds__(256, 2) void proj_kernel(const float* __restrict__ bias)
{
    extern __shared__ float sm[];
    __shared__ float sBias[128];

    const int tid = threadIdx.x;
    const int m0 = blockIdx.y * 128;
    const int n0 = blockIdx.x * 128;
    const int wid = tid >> 5;
    const int wm = wid & 1;                  // m strip of 64
    const int wn = wid >> 1;                 // n strip of 32

    if (tid < 128) sBias[tid] = bias[n0 + tid];

    wmma::fragment<wmma::accumulator, 16, 16, 8, float> acc[4][2];
#pragma unroll
    for (int i = 0; i < 4; i++)
#pragma unroll
        for (int j = 0; j < 2; j++) wmma::fill_fragment(acc[i][j], 0.f);

    const uint32_t sbase = smem_u32(sm);

    auto load_stage = [&](int s, int k0) {
        const uint32_t aB = sbase + s * (PJ_STGF * 4);
        const uint32_t bB = aB + 128 * PJ_LD * 4;
#pragma unroll
        for (int i = 0; i < 4; i++) {
            const int idx = tid + i * 256;           // 0..1023
            const int row = idx >> 3, c16 = idx & 7;
            CP_ASYNC16(aB + row * (PJ_LD * 4) + c16 * 16,
                       g_xc + (size_t)(m0 + row) * D_ + k0 + c16 * 4);
        }
#pragma unroll
        for (int i = 0; i < 4; i++) {
            const int idx = tid + i * 256;
            const int row = idx >> 3, c16 = idx & 7;
            CP_ASYNC16(bB + row * (PJ_LD * 4) + c16 * 16,
                       g_wc + (size_t)(n0 + row) * D_ + k0 + c16 * 4);
        }
        CP_COMMIT();
    };

    load_stage(0, 0);
    load_stage(1, 32);

    const int NKC = D_ / 32;                 // 32 chunks
    for (int kc = 0; kc < NKC; kc++) {
        if (kc < NKC - 1) CP_WAIT(1); else CP_WAIT(0);
        __syncthreads();

        const float* A = sm + (kc & 1) * PJ_STGF;
        const float* Bp = A + 128 * PJ_LD;
#pragma unroll
        for (int kd = 0; kd < 32; kd += 8) {
            wmma::fragment<wmma::matrix_a, 16, 16, 8, wmma::precision::tf32, wmma::row_major> af[4];
            wmma::fragment<wmma::matrix_b, 16, 16, 8, wmma::precision::tf32, wmma::col_major> bf[2];
#pragma unroll
            for (int i = 0; i < 4; i++)
                wmma::load_matrix_sync(af[i], A + (wm * 64 + i * 16) * PJ_LD + kd, PJ_LD);
#pragma unroll
            for (int j = 0; j < 2; j++)
                wmma::load_matrix_sync(bf[j], Bp + (wn * 32 + j * 16) * PJ_LD + kd, PJ_LD);
#pragma unroll
            for (int i = 0; i < 4; i++)
#pragma unroll
                for (int j = 0; j < 2; j++)
                    wmma::mma_sync(acc[i][j], af[i], bf[j], acc[i][j]);
        }
        __syncthreads();
        if (kc + 2 < NKC) load_stage(kc & 1, (kc + 2) * 32);
    }

    // ---- epilogue: frags -> Cs -> tf32-rounded scatter to g_q / g_k ----
    float* Cs = sm;                          // 128 x PJ_LDC (16896 fl <= 18432)
#pragma unroll
    for (int i = 0; i < 4; i++)
#pragma unroll
        for (int j = 0; j < 2; j++)
            wmma::store_matrix_sync(Cs + (wm * 64 + i * 16) * PJ_LDC + wn * 32 + j * 16,
                                    acc[i][j], PJ_LDC, wmma::mem_row_major);
    __syncthreads();

    {
        const int r    = tid >> 1;
        const int half = tid & 1;
        const int m = m0 + r;
        const int bb = m >> 11;
        const int s_idx = m & 2047;
        const int hh = n0 >> 7;
        const size_t base = (((size_t)bb * H_ + hh) * S_ + s_idx) * DH + half * 32;
        const float* cr = Cs + r * PJ_LDC;
#pragma unroll
        for (int g = 0; g < 4; g++) {
            const int j0c = half * 64 + g * 16;
            float qv[8], kv[8];
#pragma unroll
            for (int jj = 0; jj < 8; jj++) {
                qv[jj] = wmma::__float_to_tf32(cr[j0c + 2*jj]     + sBias[j0c + 2*jj]);
                kv[jj] = wmma::__float_to_tf32(cr[j0c + 2*jj + 1] + sBias[j0c + 2*jj + 1]);
            }
            *(float4*)(g_q + base + g * 8)     = make_float4(qv[0], qv[1], qv[2], qv[3]);
            *(float4*)(g_q + base + g * 8 + 4) = make_float4(qv[4], qv[5], qv[6], qv[7]);
            *(float4*)(g_k + base + g * 8)     = make_float4(kv[0], kv[1], kv[2], kv[3]);
            *(float4*)(g_k + base + g * 8 + 4) = make_float4(kv[4], kv[5], kv[6], kv[7]);
        }
    }
}

// ---------------------------------------------------------------------------
// Kernel 2: ksum[b,h,d] = sum_s k[b,h,s,d]
// ---------------------------------------------------------------------------
__global__ __launch_bounds__(256) void ksum_kernel()
{
    __shared__ float red[256];
    const int bh = blockIdx.x;
    const int t = threadIdx.x;
    const int d = t & 63;
    const int chunk = t >> 6;
    const float* base = g_k + (size_t)bh * S_ * DH;
    float s = 0.f;
    const int j0 = chunk * (S_ / 4), j1 = j0 + (S_ / 4);
    for (int j = j0; j < j1; j++) s += base[(size_t)j * DH + d];
    red[t] = s;
    __syncthreads();
    if (t < 64)
        g_ksum[bh * DH + t] = red[t] + red[64 + t] + red[128 + t] + red[192 + t];
}

// ---------------------------------------------------------------------------
// Kernel 3: fused attention, tf32 wmma, j-tile 64, 2 CTAs/SM.
// Per (b, h, 128 q-rows): mean_i = (scale/S) q.ksum ; P = QK^T ;
// A = selu(P*scale - mean) ; out += A @ V * S^-0.5  (V = tf32(x) slice).
// smem: qs[128][68] ks[64][68] vs[64][68] ps[128][68]  = 104448 B
// ---------------------------------------------------------------------------
#define AT_LD 68
#define AT_SMEM ((128 + 64 + 64 + 128) * AT_LD * 4)   // 104448

__global__ __launch_bounds__(256, 2) void attn_kernel(float* __restrict__ out)
{
    extern __shared__ float sm[];
    float* qs = sm;                          // 128 x 68
    float* ks = qs + 128 * AT_LD;            // 64 x 68
    float* vs = ks + 64 * AT_LD;             // 64 x 68
    float* ps = vs + 64 * AT_LD;             // 128 x 68
    __shared__ float sKsum[64];
    __shared__ float sMrow[128];

    const int b  = blockIdx.z;
    const int h  = blockIdx.y;
    const int s0 = blockIdx.x * 128;
    const int tid = threadIdx.x;
    const int wid = tid >> 5;
    const int wm = wid >> 1;                 // m strip of 32 (0..3)
    const int wn = wid & 1;                  // n strip of 32 (0..1)

    const size_t bh = (size_t)b * H_ + h;
    const float* qg = g_q + bh * S_ * DH;
    const float* kg = g_k + bh * S_ * DH;
    const float* vg = g_xc + ((size_t)b * S_) * D_ + h * DH;

    const uint32_t qsB = smem_u32(qs);
    const uint32_t ksB = smem_u32(ks);
    const uint32_t vsB = smem_u32(vs);

    // ---- load Q (128 x 64) via cp.async ----
#pragma unroll
    for (int i = 0; i < 8; i++) {
        const int idx = tid + i * 256;       // 0..2047
        const int row = idx >> 4, c16 = idx & 15;
        CP_ASYNC16(qsB + row * (AT_LD * 4) + c16 * 16,
                   qg + (size_t)(s0 + row) * DH + c16 * 4);
    }
    CP_COMMIT();
    if (tid < 64) sKsum[tid] = g_ksum[bh * DH + tid];
    CP_WAIT(0);
    __syncthreads();

    const float SCALE = 0.125f;
    if (tid < 128) {
        float s = 0.f;
        const float* qr = qs + tid * AT_LD;
#pragma unroll
        for (int d = 0; d < DH; d++) s += qr[d] * sKsum[d];
        sMrow[tid] = s * (SCALE / (float)S_);
    }

    wmma::fragment<wmma::accumulator, 16, 16, 8, float> oacc[2][2];
#pragma unroll
    for (int i = 0; i < 2; i++)
#pragma unroll
        for (int j = 0; j < 2; j++) wmma::fill_fragment(oacc[i][j], 0.f);

    for (int j0 = 0; j0 < S_; j0 += 64) {
        __syncthreads();                     // WAR on ks/vs; also covers sMrow

        // ---- load K tile (64x64) + V tile (64x64) via cp.async ----
#pragma unroll
        for (int i = 0; i < 4; i++) {
            const int idx = tid + i * 256;   // 0..1023
            const int row = idx >> 4, c16 = idx & 15;
            CP_ASYNC16(ksB + row * (AT_LD * 4) + c16 * 16,
                       kg + (size_t)(j0 + row) * DH + c16 * 4);
        }
#pragma unroll
        for (int i = 0; i < 4; i++) {
            const int idx = tid + i * 256;
            const int row = idx >> 4, c16 = idx & 15;
            CP_ASYNC16(vsB + row * (AT_LD * 4) + c16 * 16,
                       vg + (size_t)(j0 + row) * D_ + c16 * 4);
        }
        CP_COMMIT();
        CP_WAIT(0);
        __syncthreads();

        // ---- P = Q K^T  (128 x 64) ----
        wmma::fragment<wmma::accumulator, 16, 16, 8, float> pacc[2][2];
#pragma unroll
        for (int i = 0; i < 2; i++)
#pragma unroll
            for (int j = 0; j < 2; j++) wmma::fill_fragment(pacc[i][j], 0.f);

#pragma unroll
        for (int kd = 0; kd < DH; kd += 8) {
            wmma::fragment<wmma::matrix_a, 16, 16, 8, wmma::precision::tf32, wmma::row_major> af[2];
            wmma::fragment<wmma::matrix_b, 16, 16, 8, wmma::precision::tf32, wmma::col_major> bf[2];
#pragma unroll
            for (int i = 0; i < 2; i++)
                wmma::load_matrix_sync(af[i], qs + (wm * 32 + i * 16) * AT_LD + kd, AT_LD);
#pragma unroll
            for (int j = 0; j < 2; j++)
                wmma::load_matrix_sync(bf[j], ks + (wn * 32 + j * 16) * AT_LD + kd, AT_LD);
#pragma unroll
            for (int i = 0; i < 2; i++)
#pragma unroll
                for (int j = 0; j < 2; j++)
                    wmma::mma_sync(pacc[i][j], af[i], bf[j], pacc[i][j]);
        }
#pragma unroll
        for (int i = 0; i < 2; i++)
#pragma unroll
            for (int j = 0; j < 2; j++)
                wmma::store_matrix_sync(ps + (wm * 32 + i * 16) * AT_LD + wn * 32 + j * 16,
                                        pacc[i][j], AT_LD, wmma::mem_row_major);
        __syncthreads();

        // ---- A = tf32(selu(P*scale - mean)) in place ----
        {
            const int r = tid >> 1;
            const int cb = (tid & 1) * 32;
            const float mr = sMrow[r];
            float* pr = ps + r * AT_LD + cb;
#pragma unroll 8
            for (int c = 0; c < 32; c++) {
                const float s = pr[c] * SCALE - mr;
                const float v = (s > 0.f)
                    ? 1.0507009873554805f * s
                    : 1.7580993408473766f * (__expf(s) - 1.f);
                pr[c] = wmma::__float_to_tf32(v);
            }
        }
        __syncthreads();

        // ---- oacc += A @ V ----
#pragma unroll
        for (int kj = 0; kj < 64; kj += 8) {
            wmma::fragment<wmma::matrix_a, 16, 16, 8, wmma::precision::tf32, wmma::row_major> af[2];
            wmma::fragment<wmma::matrix_b, 16, 16, 8, wmma::precision::tf32, wmma::row_major> bf[2];
#pragma unroll
            for (int i = 0; i < 2; i++)
                wmma::load_matrix_sync(af[i], ps + (wm * 32 + i * 16) * AT_LD + kj, AT_LD);
#pragma unroll
            for (int j = 0; j < 2; j++)
                wmma::load_matrix_sync(bf[j], vs + kj * AT_LD + wn * 32 + j * 16, AT_LD);
#pragma unroll
            for (int i = 0; i < 2; i++)
#pragma unroll
                for (int j = 0; j < 2; j++)
                    wmma::mma_sync(oacc[i][j], af[i], bf[j], oacc[i][j]);
        }
    }
    __syncthreads();

    // ---- epilogue: oacc -> ps -> gmem ----
#pragma unroll
    for (int i = 0; i < 2; i++)
#pragma unroll
        for (int j = 0; j < 2; j++)
            wmma::store_matrix_sync(ps + (wm * 32 + i * 16) * AT_LD + wn * 32 + j * 16,
                                    oacc[i][j], AT_LD, wmma::mem_row_major);
    __syncthreads();

    {
        const float OS = 0.022097086912079608f;   // 2048^-0.5
        const int r = tid >> 1;
        const int seg = (tid & 1) * 32;
        const float* pr = ps + r * AT_LD + seg;
        float* dst = out + ((size_t)b * S_ + s0 + r) * D_ + h * DH + seg;
#pragma unroll
        for (int v = 0; v < 8; v++) {
            float4 o4 = make_float4(pr[v*4+0] * OS, pr[v*4+1] * OS,
                                    pr[v*4+2] * OS, pr[v*4+3] * OS);
            *(float4*)(dst + v * 4) = o4;
        }
    }
}

// ---------------------------------------------------------------------------
extern "C" void kernel_launch(void* const* d_in, const int* in_sizes, int n_in,
                              void* d_out, int out_size)
{
    const float* x    = (const float*)d_in[0];
    const float* W    = (const float*)d_in[1];
    const float* bias = (const float*)d_in[2];
    float* out = (float*)d_out;

    cudaFuncSetAttribute(proj_kernel,
                         cudaFuncAttributeMaxDynamicSharedMemorySize, PJ_SMEM);
    cudaFuncSetAttribute(attn_kernel,
                         cudaFuncAttributeMaxDynamicSharedMemorySize, AT_SMEM);

    const int cvt_blocks = (int)((XC_F4 + WC_F4 + 255) / 256);
    cvt_kernel<<<cvt_blocks, 256>>>(x, W);

    dim3 pg(D_ * 2 / 128, (B_ * S_) / 128);          // (16, 64)
    proj_kernel<<<pg, 256, PJ_SMEM>>>(bias);

    ksum_kernel<<<B_ * H_, 256>>>();

    dim3 ag(S_ / 128, H_, B_);                       // (16, 16, 4)
    attn_kernel<<<ag, 256, AT_SMEM>>>(out);
}

// round 5
// speedup vs baseline: 2.2166x; 1.1332x over previous
#include <cuda_runtime.h>
#include <mma.h>
#include <cstdint>

using namespace nvcuda;

#define B_  4
#define S_  2048
#define D_  1024
#define H_  16
#define DH  64

// Scratch (device globals -- no allocations allowed)
__device__ float g_q[(size_t)B_*H_*S_*DH];       // 33.5 MB (tf32-rounded q)
__device__ float g_k[(size_t)B_*H_*S_*DH];       // 33.5 MB (tf32-rounded k)
__device__ float g_xc[(size_t)B_*S_*D_];         // 33.5 MB (tf32-rounded x)
__device__ float g_wc[(size_t)2*D_*D_];          // 8.4 MB  (tf32-rounded W)
__device__ float g_ksum[B_*H_*DH];

// ---------------------------------------------------------------------------
// helpers
// ---------------------------------------------------------------------------
__device__ __forceinline__ uint32_t smem_u32(const void* p) {
    uint32_t a;
    asm("{ .reg .u64 t; cvta.to.shared.u64 t, %1; cvt.u32.u64 %0, t; }"
        : "=r"(a) : "l"(p));
    return a;
}
#define CP_ASYNC16(dst, src) \
    asm volatile("cp.async.cg.shared.global [%0], [%1], 16;" :: "r"(dst), "l"(src) : "memory")
#define CP_COMMIT() asm volatile("cp.async.commit_group;" ::: "memory")
#define CP_WAIT(N)  asm volatile("cp.async.wait_group %0;" :: "n"(N) : "memory")

// raw tf32 mma m16n8k8 (row.col), D += A*B
__device__ __forceinline__ void mma16n8k8(float* d, const uint32_t* a, const uint32_t* b)
{
    asm volatile(
        "mma.sync.aligned.m16n8k8.row.col.f32.tf32.tf32.f32 "
        "{%0,%1,%2,%3}, {%4,%5,%6,%7}, {%8,%9}, {%0,%1,%2,%3};"
        : "+f"(d[0]), "+f"(d[1]), "+f"(d[2]), "+f"(d[3])
        : "r"(a[0]), "r"(a[1]), "r"(a[2]), "r"(a[3]), "r"(b[0]), "r"(b[1]));
}

__device__ __forceinline__ float selu_f(float s)
{
    return (s > 0.f) ? 1.0507009873554805f * s
                     : 1.7580993408473766f * (__expf(s) - 1.f);
}

// ---------------------------------------------------------------------------
// Kernel 0: tf32-round x and W into scratch
// ---------------------------------------------------------------------------
#define XC_F4 ((size_t)B_*S_*D_/4)       // 2097152
#define WC_F4 ((size_t)2*D_*D_/4)        // 524288

__global__ __launch_bounds__(256) void cvt_kernel(
    const float* __restrict__ x, const float* __restrict__ W)
{
    const size_t i = (size_t)blockIdx.x * 256 + threadIdx.x;
    if (i < XC_F4) {
        float4 v = ((const float4*)x)[i];
        v.x = wmma::__float_to_tf32(v.x); v.y = wmma::__float_to_tf32(v.y);
        v.z = wmma::__float_to_tf32(v.z); v.w = wmma::__float_to_tf32(v.w);
        ((float4*)g_xc)[i] = v;
    } else if (i < XC_F4 + WC_F4) {
        const size_t j = i - XC_F4;
        float4 v = ((const float4*)W)[j];
        v.x = wmma::__float_to_tf32(v.x); v.y = wmma::__float_to_tf32(v.y);
        v.z = wmma::__float_to_tf32(v.z); v.w = wmma::__float_to_tf32(v.w);
        ((float4*)g_wc)[j] = v;
    }
}

// ---------------------------------------------------------------------------
// Kernel 1: fused q/k projection, tf32 wmma (unchanged from R4 pass)
// ---------------------------------------------------------------------------
#define PJ_LD   36
#define PJ_STGF (2 * 128 * PJ_LD)
#define PJ_SMEM (2 * PJ_STGF * 4)            // 73728 B
#define PJ_LDC  132

__global__ __launch_bounds__(256, 2) void proj_kernel(const float* __restrict__ bias)
{
    extern __shared__ float sm[];
    __shared__ float sBias[128];

    const int tid = threadIdx.x;
    const int m0 = blockIdx.y * 128;
    const int n0 = blockIdx.x * 128;
    const int wid = tid >> 5;
    const int wm = wid & 1;
    const int wn = wid >> 1;

    if (tid < 128) sBias[tid] = bias[n0 + tid];

    wmma::fragment<wmma::accumulator, 16, 16, 8, float> acc[4][2];
#pragma unroll
    for (int i = 0; i < 4; i++)
#pragma unroll
        for (int j = 0; j < 2; j++) wmma::fill_fragment(acc[i][j], 0.f);

    const uint32_t sbase = smem_u32(sm);

    auto load_stage = [&](int s, int k0) {
        const uint32_t aB = sbase + s * (PJ_STGF * 4);
        const uint32_t bB = aB + 128 * PJ_LD * 4;
#pragma unroll
        for (int i = 0; i < 4; i++) {
            const int idx = tid + i * 256;
            const int row = idx >> 3, c16 = idx & 7;
            CP_ASYNC16(aB + row * (PJ_LD * 4) + c16 * 16,
                       g_xc + (size_t)(m0 + row) * D_ + k0 + c16 * 4);
        }
#pragma unroll
        for (int i = 0; i < 4; i++) {
            const int idx = tid + i * 256;
            const int row = idx >> 3, c16 = idx & 7;
            CP_ASYNC16(bB + row * (PJ_LD * 4) + c16 * 16,
                       g_wc + (size_t)(n0 + row) * D_ + k0 + c16 * 4);
        }
        CP_COMMIT();
    };

    load_stage(0, 0);
    load_stage(1, 32);

    const int NKC = D_ / 32;
    for (int kc = 0; kc < NKC; kc++) {
        if (kc < NKC - 1) CP_WAIT(1); else CP_WAIT(0);
        __syncthreads();

        const float* A = sm + (kc & 1) * PJ_STGF;
        const float* Bp = A + 128 * PJ_LD;
#pragma unroll
        for (int kd = 0; kd < 32; kd += 8) {
            wmma::fragment<wmma::matrix_a, 16, 16, 8, wmma::precision::tf32, wmma::row_major> af[4];
            wmma::fragment<wmma::matrix_b, 16, 16, 8, wmma::precision::tf32, wmma::col_major> bf[2];
#pragma unroll
            for (int i = 0; i < 4; i++)
                wmma::load_matrix_sync(af[i], A + (wm * 64 + i * 16) * PJ_LD + kd, PJ_LD);
#pragma unroll
            for (int j = 0; j < 2; j++)
                wmma::load_matrix_sync(bf[j], Bp + (wn * 32 + j * 16) * PJ_LD + kd, PJ_LD);
#pragma unroll
            for (int i = 0; i < 4; i++)
#pragma unroll
                for (int j = 0; j < 2; j++)
                    wmma::mma_sync(acc[i][j], af[i], bf[j], acc[i][j]);
        }
        __syncthreads();
        if (kc + 2 < NKC) load_stage(kc & 1, (kc + 2) * 32);
    }

    float* Cs = sm;
#pragma unroll
    for (int i = 0; i < 4; i++)
#pragma unroll
        for (int j = 0; j < 2; j++)
            wmma::store_matrix_sync(Cs + (wm * 64 + i * 16) * PJ_LDC + wn * 32 + j * 16,
                                    acc[i][j], PJ_LDC, wmma::mem_row_major);
    __syncthreads();

    {
        const int r    = tid >> 1;
        const int half = tid & 1;
        const int m = m0 + r;
        const int bb = m >> 11;
        const int s_idx = m & 2047;
        const int hh = n0 >> 7;
        const size_t base = (((size_t)bb * H_ + hh) * S_ + s_idx) * DH + half * 32;
        const float* cr = Cs + r * PJ_LDC;
#pragma unroll
        for (int g = 0; g < 4; g++) {
            const int j0c = half * 64 + g * 16;
            float qv[8], kv[8];
#pragma unroll
            for (int jj = 0; jj < 8; jj++) {
                qv[jj] = wmma::__float_to_tf32(cr[j0c + 2*jj]     + sBias[j0c + 2*jj]);
                kv[jj] = wmma::__float_to_tf32(cr[j0c + 2*jj + 1] + sBias[j0c + 2*jj + 1]);
            }
            *(float4*)(g_q + base + g * 8)     = make_float4(qv[0], qv[1], qv[2], qv[3]);
            *(float4*)(g_q + base + g * 8 + 4) = make_float4(qv[4], qv[5], qv[6], qv[7]);
            *(float4*)(g_k + base + g * 8)     = make_float4(kv[0], kv[1], kv[2], kv[3]);
            *(float4*)(g_k + base + g * 8 + 4) = make_float4(kv[4], kv[5], kv[6], kv[7]);
        }
    }
}

// ---------------------------------------------------------------------------
// Kernel 2: ksum[b,h,d] = sum_s k[b,h,s,d]
// ---------------------------------------------------------------------------
__global__ __launch_bounds__(256) void ksum_kernel()
{
    __shared__ float red[256];
    const int bh = blockIdx.x;
    const int t = threadIdx.x;
    const int d = t & 63;
    const int chunk = t >> 6;
    const float* base = g_k + (size_t)bh * S_ * DH;
    float s = 0.f;
    const int j0 = chunk * (S_ / 4), j1 = j0 + (S_ / 4);
    for (int j = j0; j < j1; j++) s += base[(size_t)j * DH + d];
    red[t] = s;
    __syncthreads();
    if (t < 64)
        g_ksum[bh * DH + t] = red[t] + red[64 + t] + red[128 + t] + red[192 + t];
}

// ---------------------------------------------------------------------------
// Kernel 3: fused attention.  512 threads, j-tile 64, double-buffered K/V
// cp.async pipeline, QK^T via raw mma.m16n8k8 with selu fused in registers,
// AV via wmma.  Per (b, h, 128 q-rows).
// smem: qs[128][68], ks[2][64][68], vs[2][64][68], ps[128][68]  = 139264 B
// ---------------------------------------------------------------------------
#define AT_LD 68
#define AT_SMEM (512 * AT_LD * 4)            // 139264

__global__ __launch_bounds__(512, 1) void attn_kernel(float* __restrict__ out)
{
    extern __shared__ float sm[];
    float* qs  = sm;                         // 128 x 68
    float* ksb = qs + 128 * AT_LD;           // 2 x 64 x 68
    float* vsb = ksb + 2 * 64 * AT_LD;       // 2 x 64 x 68
    float* ps  = vsb + 2 * 64 * AT_LD;       // 128 x 68
    __shared__ float sKsum[64];
    __shared__ float sMrow[128];

    const int b  = blockIdx.z;
    const int h  = blockIdx.y;
    const int s0 = blockIdx.x * 128;
    const int tid = threadIdx.x;
    const int wid = tid >> 5;
    const int lane = tid & 31;
    const int gid = lane >> 2;               // 0..7
    const int tig = lane & 3;                // 0..3
    const int wm = wid >> 2;                 // m strip of 32 (0..3)
    const int wn = wid & 3;                  // n strip of 16 (0..3)

    const size_t bh = (size_t)b * H_ + h;
    const float* qg = g_q + bh * S_ * DH;
    const float* kg = g_k + bh * S_ * DH;
    const float* vg = g_xc + ((size_t)b * S_) * D_ + h * DH;

    const uint32_t qsB = smem_u32(qs);
    const uint32_t ksB = smem_u32(ksb);
    const uint32_t vsB = smem_u32(vsb);

    auto load_kv = [&](int buf, int j0) {
        const uint32_t kB = ksB + buf * (64 * AT_LD * 4);
        const uint32_t vB = vsB + buf * (64 * AT_LD * 4);
#pragma unroll
        for (int i = 0; i < 2; i++) {
            const int idx = tid + i * 512;   // 0..1023
            const int row = idx >> 4, c16 = idx & 15;
            CP_ASYNC16(kB + row * (AT_LD * 4) + c16 * 16,
                       kg + (size_t)(j0 + row) * DH + c16 * 4);
        }
#pragma unroll
        for (int i = 0; i < 2; i++) {
            const int idx = tid + i * 512;
            const int row = idx >> 4, c16 = idx & 15;
            CP_ASYNC16(vB + row * (AT_LD * 4) + c16 * 16,
                       vg + (size_t)(j0 + row) * D_ + c16 * 4);
        }
    };

    // ---- prologue: Q + K/V tile 0 ----
#pragma unroll
    for (int i = 0; i < 4; i++) {
        const int idx = tid + i * 512;       // 0..2047
        const int row = idx >> 4, c16 = idx & 15;
        CP_ASYNC16(qsB + row * (AT_LD * 4) + c16 * 16,
                   qg + (size_t)(s0 + row) * DH + c16 * 4);
    }
    load_kv(0, 0);
    CP_COMMIT();
    if (tid < 64) sKsum[tid] = g_ksum[bh * DH + tid];
    CP_WAIT(0);
    __syncthreads();

    const float SCALE = 0.125f;
    if (tid < 128) {
        float s = 0.f;
        const float* qr = qs + tid * AT_LD;
#pragma unroll
        for (int d = 0; d < DH; d++) s += qr[d] * sKsum[d];
        sMrow[tid] = s * (SCALE / (float)S_);
    }
    __syncthreads();

    // per-thread fixed mean rows (m16n8 acc rows: base+gid, base+gid+8)
    float mr[2][2];
#pragma unroll
    for (int tm = 0; tm < 2; tm++) {
        const int r0 = wm * 32 + tm * 16 + gid;
        mr[tm][0] = sMrow[r0];
        mr[tm][1] = sMrow[r0 + 8];
    }

    wmma::fragment<wmma::accumulator, 16, 16, 8, float> oacc[2];
#pragma unroll
    for (int i = 0; i < 2; i++) wmma::fill_fragment(oacc[i], 0.f);

    const int NJT = S_ / 64;                 // 32
    for (int jt = 0; jt < NJT; jt++) {
        const int buf = jt & 1;
        if (jt + 1 < NJT) {
            load_kv(buf ^ 1, (jt + 1) * 64);
            CP_COMMIT();
            CP_WAIT(1);
        } else {
            CP_WAIT(0);
        }
        __syncthreads();                     // (a) K/V[buf] visible; ps free

        const float* kss = ksb + buf * (64 * AT_LD);
        const float* vss = vsb + buf * (64 * AT_LD);

        // ---- P = Q K^T via raw mma, 2m x 2n tiles of 16x8 ----
        float d[2][2][4];
#pragma unroll
        for (int tm = 0; tm < 2; tm++)
#pragma unroll
            for (int tn = 0; tn < 2; tn++)
#pragma unroll
                for (int r = 0; r < 4; r++) d[tm][tn][r] = 0.f;

#pragma unroll
        for (int kd = 0; kd < DH; kd += 8) {
            uint32_t a[2][4], bb2[2][2];
#pragma unroll
            for (int tm = 0; tm < 2; tm++) {
                const float* qb = qs + (wm * 32 + tm * 16 + gid) * AT_LD + kd + tig;
                a[tm][0] = __float_as_uint(qb[0]);
                a[tm][1] = __float_as_uint(qb[8 * AT_LD]);
                a[tm][2] = __float_as_uint(qb[4]);
                a[tm][3] = __float_as_uint(qb[8 * AT_LD + 4]);
            }
#pragma unroll
            for (int tn = 0; tn < 2; tn++) {
                const float* kb = kss + (wn * 16 + tn * 8 + gid) * AT_LD + kd + tig;
                bb2[tn][0] = __float_as_uint(kb[0]);
                bb2[tn][1] = __float_as_uint(kb[4]);
            }
#pragma unroll
            for (int tm = 0; tm < 2; tm++)
#pragma unroll
                for (int tn = 0; tn < 2; tn++)
                    mma16n8k8(d[tm][tn], a[tm], bb2[tn]);
        }

        // ---- selu in registers, store tf32 A to ps ----
#pragma unroll
        for (int tm = 0; tm < 2; tm++) {
            const int r0 = wm * 32 + tm * 16 + gid;
#pragma unroll
            for (int tn = 0; tn < 2; tn++) {
                const int cb = wn * 16 + tn * 8 + tig * 2;
                float v0 = selu_f(d[tm][tn][0] * SCALE - mr[tm][0]);
                float v1 = selu_f(d[tm][tn][1] * SCALE - mr[tm][0]);
                float v2 = selu_f(d[tm][tn][2] * SCALE - mr[tm][1]);
                float v3 = selu_f(d[tm][tn][3] * SCALE - mr[tm][1]);
                *(float2*)(ps + r0 * AT_LD + cb) =
                    make_float2(wmma::__float_to_tf32(v0), wmma::__float_to_tf32(v1));
                *(float2*)(ps + (r0 + 8) * AT_LD + cb) =
                    make_float2(wmma::__float_to_tf32(v2), wmma::__float_to_tf32(v3));
            }
        }
        __syncthreads();                     // (b) ps complete

        // ---- oacc += A @ V  (warp tile 32m x 16n) ----
#pragma unroll
        for (int kj = 0; kj < 64; kj += 8) {
            wmma::fragment<wmma::matrix_a, 16, 16, 8, wmma::precision::tf32, wmma::row_major> af[2];
            wmma::fragment<wmma::matrix_b, 16, 16, 8, wmma::precision::tf32, wmma::row_major> bf;
#pragma unroll
            for (int i = 0; i < 2; i++)
                wmma::load_matrix_sync(af[i], ps + (wm * 32 + i * 16) * AT_LD + kj, AT_LD);
            wmma::load_matrix_sync(bf, vss + kj * AT_LD + wn * 16, AT_LD);
#pragma unroll
            for (int i = 0; i < 2; i++)
                wmma::mma_sync(oacc[i], af[i], bf, oacc[i]);
        }
        __syncthreads();                     // (d) buffers + ps free for next iter
    }

    // ---- epilogue: oacc -> ps -> gmem ----
#pragma unroll
    for (int i = 0; i < 2; i++)
        wmma::store_matrix_sync(ps + (wm * 32 + i * 16) * AT_LD + wn * 16,
                                oacc[i], AT_LD, wmma::mem_row_major);
    __syncthreads();

    {
        const float OS = 0.022097086912079608f;   // 2048^-0.5
        const int r = tid >> 2;
        const int seg = (tid & 3) * 16;
        const float* pr = ps + r * AT_LD + seg;
        float* dst = out + ((size_t)b * S_ + s0 + r) * D_ + h * DH + seg;
#pragma unroll
        for (int v = 0; v < 4; v++) {
            float4 o4 = make_float4(pr[v*4+0] * OS, pr[v*4+1] * OS,
                                    pr[v*4+2] * OS, pr[v*4+3] * OS);
            *(float4*)(dst + v * 4) = o4;
        }
    }
}

// ---------------------------------------------------------------------------
extern "C" void kernel_launch(void* const* d_in, const int* in_sizes, int n_in,
                              void* d_out, int out_size)
{
    const float* x    = (const float*)d_in[0];
    const float* W    = (const float*)d_in[1];
    const float* bias = (const float*)d_in[2];
    float* out = (float*)d_out;

    cudaFuncSetAttribute(proj_kernel,
                         cudaFuncAttributeMaxDynamicSharedMemorySize, PJ_SMEM);
    cudaFuncSetAttribute(attn_kernel,
                         cudaFuncAttributeMaxDynamicSharedMemorySize, AT_SMEM);

    const int cvt_blocks = (int)((XC_F4 + WC_F4 + 255) / 256);
    cvt_kernel<<<cvt_blocks, 256>>>(x, W);

    dim3 pg(D_ * 2 / 128, (B_ * S_) / 128);          // (16, 64)
    proj_kernel<<<pg, 256, PJ_SMEM>>>(bias);

    ksum_kernel<<<B_ * H_, 256>>>();

    dim3 ag(S_ / 128, H_, B_);                       // (16, 16, 4)
    attn_kernel<<<ag, 512, AT_SMEM>>>(out);
}

// round 6
// speedup vs baseline: 2.8211x; 1.2727x over previous
#include <cuda_runtime.h>
#include <mma.h>
#include <cstdint>

using namespace nvcuda;

#define B_  4
#define S_  2048
#define D_  1024
#define H_  16
#define DH  64

// Scratch (device globals -- no allocations allowed)
__device__ float g_q[(size_t)B_*H_*S_*DH];       // 33.5 MB (tf32-rounded q)
__device__ float g_k[(size_t)B_*H_*S_*DH];       // 33.5 MB (tf32-rounded k)
__device__ float g_xc[(size_t)B_*S_*D_];         // 33.5 MB (tf32-rounded x)
__device__ float g_wc[(size_t)2*D_*D_];          // 8.4 MB  (tf32-rounded W)
__device__ float g_ksum[B_*H_*DH];

// ---------------------------------------------------------------------------
// helpers
// ---------------------------------------------------------------------------
__device__ __forceinline__ uint32_t smem_u32(const void* p) {
    uint32_t a;
    asm("{ .reg .u64 t; cvta.to.shared.u64 t, %1; cvt.u32.u64 %0, t; }"
        : "=r"(a) : "l"(p));
    return a;
}
#define CP_ASYNC16(dst, src) \
    asm volatile("cp.async.cg.shared.global [%0], [%1], 16;" :: "r"(dst), "l"(src) : "memory")
#define CP_COMMIT() asm volatile("cp.async.commit_group;" ::: "memory")
#define CP_WAIT(N)  asm volatile("cp.async.wait_group %0;" :: "n"(N) : "memory")

// raw tf32 mma m16n8k8 (row.col), D += A*B
__device__ __forceinline__ void mma16n8k8(float* d, const uint32_t* a, const uint32_t* b)
{
    asm volatile(
        "mma.sync.aligned.m16n8k8.row.col.f32.tf32.tf32.f32 "
        "{%0,%1,%2,%3}, {%4,%5,%6,%7}, {%8,%9}, {%0,%1,%2,%3};"
        : "+f"(d[0]), "+f"(d[1]), "+f"(d[2]), "+f"(d[3])
        : "r"(a[0]), "r"(a[1]), "r"(a[2]), "r"(a[3]), "r"(b[0]), "r"(b[1]));
}

__device__ __forceinline__ float selu_f(float s)
{
    return (s > 0.f) ? 1.0507009873554805f * s
                     : 1.7580993408473766f * (__expf(s) - 1.f);
}

// ---------------------------------------------------------------------------
// Kernel 0: tf32-round x and W into scratch
// ---------------------------------------------------------------------------
#define XC_F4 ((size_t)B_*S_*D_/4)       // 2097152
#define WC_F4 ((size_t)2*D_*D_/4)        // 524288

__global__ __launch_bounds__(256) void cvt_kernel(
    const float* __restrict__ x, const float* __restrict__ W)
{
    const size_t i = (size_t)blockIdx.x * 256 + threadIdx.x;
    if (i < XC_F4) {
        float4 v = ((const float4*)x)[i];
        v.x = wmma::__float_to_tf32(v.x); v.y = wmma::__float_to_tf32(v.y);
        v.z = wmma::__float_to_tf32(v.z); v.w = wmma::__float_to_tf32(v.w);
        ((float4*)g_xc)[i] = v;
    } else if (i < XC_F4 + WC_F4) {
        const size_t j = i - XC_F4;
        float4 v = ((const float4*)W)[j];
        v.x = wmma::__float_to_tf32(v.x); v.y = wmma::__float_to_tf32(v.y);
        v.z = wmma::__float_to_tf32(v.z); v.w = wmma::__float_to_tf32(v.w);
        ((float4*)g_wc)[j] = v;
    }
}

// ---------------------------------------------------------------------------
// Kernel 1: fused q/k projection, tf32 wmma (unchanged -- passing at R5)
// ---------------------------------------------------------------------------
#define PJ_LD   36
#define PJ_STGF (2 * 128 * PJ_LD)
#define PJ_SMEM (2 * PJ_STGF * 4)            // 73728 B
#define PJ_LDC  132

__global__ __launch_bounds__(256, 2) void proj_kernel(const float* __restrict__ bias)
{
    extern __shared__ float sm[];
    __shared__ float sBias[128];

    const int tid = threadIdx.x;
    const int m0 = blockIdx.y * 128;
    const int n0 = blockIdx.x * 128;
    const int wid = tid >> 5;
    const int wm = wid & 1;
    const int wn = wid >> 1;

    if (tid < 128) sBias[tid] = bias[n0 + tid];

    wmma::fragment<wmma::accumulator, 16, 16, 8, float> acc[4][2];
#pragma unroll
    for (int i = 0; i < 4; i++)
#pragma unroll
        for (int j = 0; j < 2; j++) wmma::fill_fragment(acc[i][j], 0.f);

    const uint32_t sbase = smem_u32(sm);

    auto load_stage = [&](int s, int k0) {
        const uint32_t aB = sbase + s * (PJ_STGF * 4);
        const uint32_t bB = aB + 128 * PJ_LD * 4;
#pragma unroll
        for (int i = 0; i < 4; i++) {
            const int idx = tid + i * 256;
            const int row = idx >> 3, c16 = idx & 7;
            CP_ASYNC16(aB + row * (PJ_LD * 4) + c16 * 16,
                       g_xc + (size_t)(m0 + row) * D_ + k0 + c16 * 4);
        }
#pragma unroll
        for (int i = 0; i < 4; i++) {
            const int idx = tid + i * 256;
            const int row = idx >> 3, c16 = idx & 7;
            CP_ASYNC16(bB + row * (PJ_LD * 4) + c16 * 16,
                       g_wc + (size_t)(n0 + row) * D_ + k0 + c16 * 4);
        }
        CP_COMMIT();
    };

    load_stage(0, 0);
    load_stage(1, 32);

    const int NKC = D_ / 32;
    for (int kc = 0; kc < NKC; kc++) {
        if (kc < NKC - 1) CP_WAIT(1); else CP_WAIT(0);
        __syncthreads();

        const float* A = sm + (kc & 1) * PJ_STGF;
        const float* Bp = A + 128 * PJ_LD;
#pragma unroll
        for (int kd = 0; kd < 32; kd += 8) {
            wmma::fragment<wmma::matrix_a, 16, 16, 8, wmma::precision::tf32, wmma::row_major> af[4];
            wmma::fragment<wmma::matrix_b, 16, 16, 8, wmma::precision::tf32, wmma::col_major> bf[2];
#pragma unroll
            for (int i = 0; i < 4; i++)
                wmma::load_matrix_sync(af[i], A + (wm * 64 + i * 16) * PJ_LD + kd, PJ_LD);
#pragma unroll
            for (int j = 0; j < 2; j++)
                wmma::load_matrix_sync(bf[j], Bp + (wn * 32 + j * 16) * PJ_LD + kd, PJ_LD);
#pragma unroll
            for (int i = 0; i < 4; i++)
#pragma unroll
                for (int j = 0; j < 2; j++)
                    wmma::mma_sync(acc[i][j], af[i], bf[j], acc[i][j]);
        }
        __syncthreads();
        if (kc + 2 < NKC) load_stage(kc & 1, (kc + 2) * 32);
    }

    float* Cs = sm;
#pragma unroll
    for (int i = 0; i < 4; i++)
#pragma unroll
        for (int j = 0; j < 2; j++)
            wmma::store_matrix_sync(Cs + (wm * 64 + i * 16) * PJ_LDC + wn * 32 + j * 16,
                                    acc[i][j], PJ_LDC, wmma::mem_row_major);
    __syncthreads();

    {
        const int r    = tid >> 1;
        const int half = tid & 1;
        const int m = m0 + r;
        const int bb = m >> 11;
        const int s_idx = m & 2047;
        const int hh = n0 >> 7;
        const size_t base = (((size_t)bb * H_ + hh) * S_ + s_idx) * DH + half * 32;
        const float* cr = Cs + r * PJ_LDC;
#pragma unroll
        for (int g = 0; g < 4; g++) {
            const int j0c = half * 64 + g * 16;
            float qv[8], kv[8];
#pragma unroll
            for (int jj = 0; jj < 8; jj++) {
                qv[jj] = wmma::__float_to_tf32(cr[j0c + 2*jj]     + sBias[j0c + 2*jj]);
                kv[jj] = wmma::__float_to_tf32(cr[j0c + 2*jj + 1] + sBias[j0c + 2*jj + 1]);
            }
            *(float4*)(g_q + base + g * 8)     = make_float4(qv[0], qv[1], qv[2], qv[3]);
            *(float4*)(g_q + base + g * 8 + 4) = make_float4(qv[4], qv[5], qv[6], qv[7]);
            *(float4*)(g_k + base + g * 8)     = make_float4(kv[0], kv[1], kv[2], kv[3]);
            *(float4*)(g_k + base + g * 8 + 4) = make_float4(kv[4], kv[5], kv[6], kv[7]);
        }
    }
}

// ---------------------------------------------------------------------------
// Kernel 2: ksum[b,h,d] = sum_s k[b,h,s,d]
// ---------------------------------------------------------------------------
__global__ __launch_bounds__(256) void ksum_kernel()
{
    __shared__ float red[256];
    const int bh = blockIdx.x;
    const int t = threadIdx.x;
    const int d = t & 63;
    const int chunk = t >> 6;
    const float* base = g_k + (size_t)bh * S_ * DH;
    float s = 0.f;
    const int j0 = chunk * (S_ / 4), j1 = j0 + (S_ / 4);
    for (int j = j0; j < j1; j++) s += base[(size_t)j * DH + d];
    red[t] = s;
    __syncthreads();
    if (t < 64)
        g_ksum[bh * DH + t] = red[t] + red[64 + t] + red[128 + t] + red[192 + t];
}

// ---------------------------------------------------------------------------
// Kernel 3: fused attention, register-resident A pipeline.
// 512 threads = 16 warps: wm = wid>>1 (m strip of 16), wn = wid&1 (j half).
// Per j-tile of 64: warp computes P (16x32) via raw mma, selu in regs,
// acc->A layout shuffle, partial AV over its 32 j's into persistent oacc.
// End: 2-round smem reduction over wn, then store.
// smem floats: qs 128x68, ks 2x64x68, vs 2x64x72, ps 128x68
// ---------------------------------------------------------------------------
#define AT_LD  68
#define AT_LDV 72
#define AT_QS_F   (128 * AT_LD)
#define AT_KS_F   (64 * AT_LD)
#define AT_VS_F   (64 * AT_LDV)
#define AT_SMEM ((AT_QS_F + 2 * AT_KS_F + 2 * AT_VS_F + 128 * AT_LD) * 4)  // 141312

__global__ __launch_bounds__(512, 1) void attn_kernel(float* __restrict__ out)
{
    extern __shared__ float sm[];
    float* qs  = sm;                          // 128 x 68
    float* ksb = qs + AT_QS_F;                // 2 x 64 x 68
    float* vsb = ksb + 2 * AT_KS_F;           // 2 x 64 x 72
    float* ps  = vsb + 2 * AT_VS_F;           // 128 x 68 (final reduction only)
    __shared__ float sKsum[64];
    __shared__ float sMrow[128];

    const int b  = blockIdx.z;
    const int h  = blockIdx.y;
    const int s0 = blockIdx.x * 128;
    const int tid = threadIdx.x;
    const int wid = tid >> 5;
    const int lane = tid & 31;
    const int gid = lane >> 2;               // 0..7
    const int tig = lane & 3;                // 0..3
    const int wm = wid >> 1;                 // m strip of 16 (0..7)
    const int wn = wid & 1;                  // j half of 32 (0..1)

    const size_t bh = (size_t)b * H_ + h;
    const float* qg = g_q + bh * S_ * DH;
    const float* kg = g_k + bh * S_ * DH;
    const float* vg = g_xc + ((size_t)b * S_) * D_ + h * DH;

    const uint32_t qsB = smem_u32(qs);
    const uint32_t ksB = smem_u32(ksb);
    const uint32_t vsB = smem_u32(vsb);

    auto load_kv = [&](int buf, int j0) {
        const uint32_t kB = ksB + buf * (AT_KS_F * 4);
        const uint32_t vB = vsB + buf * (AT_VS_F * 4);
#pragma unroll
        for (int i = 0; i < 2; i++) {
            const int idx = tid + i * 512;   // 0..1023
            const int row = idx >> 4, c16 = idx & 15;
            CP_ASYNC16(kB + row * (AT_LD * 4) + c16 * 16,
                       kg + (size_t)(j0 + row) * DH + c16 * 4);
        }
#pragma unroll
        for (int i = 0; i < 2; i++) {
            const int idx = tid + i * 512;
            const int row = idx >> 4, c16 = idx & 15;
            CP_ASYNC16(vB + row * (AT_LDV * 4) + c16 * 16,
                       vg + (size_t)(j0 + row) * D_ + c16 * 4);
        }
    };

    // ---- prologue: Q + K/V tile 0 ----
#pragma unroll
    for (int i = 0; i < 4; i++) {
        const int idx = tid + i * 512;       // 0..2047
        const int row = idx >> 4, c16 = idx & 15;
        CP_ASYNC16(qsB + row * (AT_LD * 4) + c16 * 16,
                   qg + (size_t)(s0 + row) * DH + c16 * 4);
    }
    load_kv(0, 0);
    CP_COMMIT();
    if (tid < 64) sKsum[tid] = g_ksum[bh * DH + tid];
    CP_WAIT(0);
    __syncthreads();

    const float SCALE = 0.125f;
    if (tid < 128) {
        float s = 0.f;
        const float* qr = qs + tid * AT_LD;
#pragma unroll
        for (int d = 0; d < DH; d++) s += qr[d] * sKsum[d];
        sMrow[tid] = s * (SCALE / (float)S_);
    }
    __syncthreads();

    const float mr0 = sMrow[wm * 16 + gid];
    const float mr1 = sMrow[wm * 16 + gid + 8];

    float oacc[8][4];
#pragma unroll
    for (int nt = 0; nt < 8; nt++)
#pragma unroll
        for (int r = 0; r < 4; r++) oacc[nt][r] = 0.f;

    const int srcA = (lane & ~3) + (tig >> 1);
    const int srcB = srcA + 2;
    const bool odd = (tig & 1) != 0;

    const int NJT = S_ / 64;                 // 32
    for (int jt = 0; jt < NJT; jt++) {
        const int buf = jt & 1;
        CP_WAIT(0);
        __syncthreads();                     // K/V[buf] visible; prev buf^1 reads done
        if (jt + 1 < NJT) {
            load_kv(buf ^ 1, (jt + 1) * 64);
            CP_COMMIT();
        }

        const float* kss = ksb + buf * AT_KS_F;
        const float* vss = vsb + buf * AT_VS_F;

        // ---- P = Q K^T : 16m x 32j (4 n-subtiles of 8) ----
        float d[4][4];
#pragma unroll
        for (int tn = 0; tn < 4; tn++)
#pragma unroll
            for (int r = 0; r < 4; r++) d[tn][r] = 0.f;

#pragma unroll
        for (int kd = 0; kd < DH; kd += 8) {
            uint32_t a[4];
            const float* qb = qs + (wm * 16 + gid) * AT_LD + kd + tig;
            a[0] = __float_as_uint(qb[0]);
            a[1] = __float_as_uint(qb[8 * AT_LD]);
            a[2] = __float_as_uint(qb[4]);
            a[3] = __float_as_uint(qb[8 * AT_LD + 4]);
#pragma unroll
            for (int tn = 0; tn < 4; tn++) {
                uint32_t bb2[2];
                const float* kb = kss + (wn * 32 + tn * 8 + gid) * AT_LD + kd + tig;
                bb2[0] = __float_as_uint(kb[0]);
                bb2[1] = __float_as_uint(kb[4]);
                mma16n8k8(d[tn], a, bb2);
            }
        }

        // ---- selu in regs, shuffle acc-layout -> A-operand layout ----
        uint32_t av[4][4];
#pragma unroll
        for (int tn = 0; tn < 4; tn++) {
            const float c0 = selu_f(d[tn][0] * SCALE - mr0);
            const float c1 = selu_f(d[tn][1] * SCALE - mr0);
            const float c2 = selu_f(d[tn][2] * SCALE - mr1);
            const float c3 = selu_f(d[tn][3] * SCALE - mr1);
            float s0 = __shfl_sync(0xffffffffu, c0, srcA);
            float s1 = __shfl_sync(0xffffffffu, c1, srcA);
            const float t0 = odd ? s1 : s0;              // (gid, tig)
            s0 = __shfl_sync(0xffffffffu, c2, srcA);
            s1 = __shfl_sync(0xffffffffu, c3, srcA);
            const float t1 = odd ? s1 : s0;              // (gid+8, tig)
            s0 = __shfl_sync(0xffffffffu, c0, srcB);
            s1 = __shfl_sync(0xffffffffu, c1, srcB);
            const float t2 = odd ? s1 : s0;              // (gid, tig+4)
            s0 = __shfl_sync(0xffffffffu, c2, srcB);
            s1 = __shfl_sync(0xffffffffu, c3, srcB);
            const float t3 = odd ? s1 : s0;              // (gid+8, tig+4)
            av[tn][0] = __float_as_uint(wmma::__float_to_tf32(t0));
            av[tn][1] = __float_as_uint(wmma::__float_to_tf32(t1));
            av[tn][2] = __float_as_uint(wmma::__float_to_tf32(t2));
            av[tn][3] = __float_as_uint(wmma::__float_to_tf32(t3));
        }

        // ---- partial AV over this warp's 32 j's ----
#pragma unroll
        for (int s = 0; s < 4; s++) {
            const float* vrow = vss + (wn * 32 + s * 8 + tig) * AT_LDV;
#pragma unroll
            for (int nt = 0; nt < 8; nt++) {
                uint32_t bb2[2];
                bb2[0] = __float_as_uint(vrow[nt * 8 + gid]);
                bb2[1] = __float_as_uint(vrow[4 * AT_LDV + nt * 8 + gid]);
                mma16n8k8(oacc[nt], av[s], bb2);
            }
        }
    }

    // ---- reduce partials across wn (2 rounds) into ps ----
    __syncthreads();
    if (wn == 0) {
#pragma unroll
        for (int nt = 0; nt < 8; nt++) {
            *(float2*)(ps + (wm * 16 + gid) * AT_LD + nt * 8 + 2 * tig) =
                make_float2(oacc[nt][0], oacc[nt][1]);
            *(float2*)(ps + (wm * 16 + gid + 8) * AT_LD + nt * 8 + 2 * tig) =
                make_float2(oacc[nt][2], oacc[nt][3]);
        }
    }
    __syncthreads();
    if (wn == 1) {
#pragma unroll
        for (int nt = 0; nt < 8; nt++) {
            float2* p0 = (float2*)(ps + (wm * 16 + gid) * AT_LD + nt * 8 + 2 * tig);
            float2* p1 = (float2*)(ps + (wm * 16 + gid + 8) * AT_LD + nt * 8 + 2 * tig);
            float2 v0 = *p0, v1 = *p1;
            v0.x += oacc[nt][0]; v0.y += oacc[nt][1];
            v1.x += oacc[nt][2]; v1.y += oacc[nt][3];
            *p0 = v0; *p1 = v1;
        }
    }
    __syncthreads();

    // ---- epilogue: ps -> gmem ----
    {
        const float OS = 0.022097086912079608f;   // 2048^-0.5
        const int r = tid >> 2;
        const int seg = (tid & 3) * 16;
        const float* pr = ps + r * AT_LD + seg;
        float* dst = out + ((size_t)b * S_ + s0 + r) * D_ + h * DH + seg;
#pragma unroll
        for (int v = 0; v < 4; v++) {
            float4 o4 = make_float4(pr[v*4+0] * OS, pr[v*4+1] * OS,
                                    pr[v*4+2] * OS, pr[v*4+3] * OS);
            *(float4*)(dst + v * 4) = o4;
        }
    }
}

// ---------------------------------------------------------------------------
extern "C" void kernel_launch(void* const* d_in, const int* in_sizes, int n_in,
                              void* d_out, int out_size)
{
    const float* x    = (const float*)d_in[0];
    const float* W    = (const float*)d_in[1];
    const float* bias = (const float*)d_in[2];
    float* out = (float*)d_out;

    cudaFuncSetAttribute(proj_kernel,
                         cudaFuncAttributeMaxDynamicSharedMemorySize, PJ_SMEM);
    cudaFuncSetAttribute(attn_kernel,
                         cudaFuncAttributeMaxDynamicSharedMemorySize, AT_SMEM);

    const int cvt_blocks = (int)((XC_F4 + WC_F4 + 255) / 256);
    cvt_kernel<<<cvt_blocks, 256>>>(x, W);

    dim3 pg(D_ * 2 / 128, (B_ * S_) / 128);          // (16, 64)
    proj_kernel<<<pg, 256, PJ_SMEM>>>(bias);

    ksum_kernel<<<B_ * H_, 256>>>();

    dim3 ag(S_ / 128, H_, B_);                       // (16, 16, 4)
    attn_kernel<<<ag, 512, AT_SMEM>>>(out);
}

// round 7
// speedup vs baseline: 3.6309x; 1.2871x over previous
#include <cuda_runtime.h>
#include <mma.h>
#include <cstdint>

using namespace nvcuda;

#define B_  4
#define S_  2048
#define D_  1024
#define H_  16
#define DH  64

// Scratch (device globals -- no allocations allowed).
// All k-dims stored PERMUTED: within each 8-block, position p holds
// dim 8g + ((p&7)>>1) + 4*(p&1)  -> fragment pairs (c, c+4) are adjacent.
__device__ float g_q[(size_t)B_*H_*S_*DH];       // perm q
__device__ float g_k[(size_t)B_*H_*S_*DH];       // perm k
__device__ float g_v[(size_t)B_*H_*DH*S_];       // V^T: [bh][d][j-perm]
__device__ float g_xc[(size_t)B_*S_*D_];         // perm tf32 x
__device__ float g_wc[(size_t)2*D_*D_];          // perm tf32 W
__device__ float g_ksum[B_*H_*DH];               // perm layout (sum of g_k rows)

// ---------------------------------------------------------------------------
// helpers
// ---------------------------------------------------------------------------
__device__ __forceinline__ uint32_t smem_u32(const void* p) {
    uint32_t a;
    asm("{ .reg .u64 t; cvta.to.shared.u64 t, %1; cvt.u32.u64 %0, t; }"
        : "=r"(a) : "l"(p));
    return a;
}
#define CP_ASYNC16(dst, src) \
    asm volatile("cp.async.cg.shared.global [%0], [%1], 16;" :: "r"(dst), "l"(src) : "memory")
#define CP_COMMIT() asm volatile("cp.async.commit_group;" ::: "memory")
#define CP_WAIT(N)  asm volatile("cp.async.wait_group %0;" :: "n"(N) : "memory")

__device__ __forceinline__ void mma16n8k8(float* d, const uint32_t* a, const uint32_t* b)
{
    asm volatile(
        "mma.sync.aligned.m16n8k8.row.col.f32.tf32.tf32.f32 "
        "{%0,%1,%2,%3}, {%4,%5,%6,%7}, {%8,%9}, {%0,%1,%2,%3};"
        : "+f"(d[0]), "+f"(d[1]), "+f"(d[2]), "+f"(d[3])
        : "r"(a[0]), "r"(a[1]), "r"(a[2]), "r"(a[3]), "r"(b[0]), "r"(b[1]));
}

__device__ __forceinline__ float selu_f(float s)
{
    return (s > 0.f) ? 1.0507009873554805f * s
                     : 1.7580993408473766f * (__expf(s) - 1.f);
}

// ---------------------------------------------------------------------------
// Kernel 0: tf32-round + 8-block permute x and W into g_xc / g_wc.
// Per 8-block: out = (a.x,b.x,a.y,b.y, a.z,b.z,a.w,b.w) of in float4s a,b.
// ---------------------------------------------------------------------------
#define X_BLK ((size_t)B_*S_*D_/8)       // 1048576
#define W_BLK ((size_t)2*D_*D_/8)        // 262144

__global__ __launch_bounds__(256) void cvt_kernel(
    const float* __restrict__ x, const float* __restrict__ W)
{
    const size_t i = (size_t)blockIdx.x * 256 + threadIdx.x;
    const float* src; float* dst;
    if (i < X_BLK)               { src = x + i * 8;            dst = g_xc + i * 8; }
    else if (i < X_BLK + W_BLK)  { src = W + (i - X_BLK) * 8;  dst = g_wc + (i - X_BLK) * 8; }
    else return;
    float4 a = *(const float4*)src;
    float4 b = *(const float4*)(src + 4);
    float4 o1 = make_float4(wmma::__float_to_tf32(a.x), wmma::__float_to_tf32(b.x),
                            wmma::__float_to_tf32(a.y), wmma::__float_to_tf32(b.y));
    float4 o2 = make_float4(wmma::__float_to_tf32(a.z), wmma::__float_to_tf32(b.z),
                            wmma::__float_to_tf32(a.w), wmma::__float_to_tf32(b.w));
    *(float4*)dst = o1;
    *(float4*)(dst + 4) = o2;
}

// ---------------------------------------------------------------------------
// Kernel 0b: V^T with j-permutation: g_v[bh][d][p] = tf32(x[b][j(p)][h*64+d])
// ---------------------------------------------------------------------------
__global__ __launch_bounds__(256) void vtr_kernel(const float* __restrict__ x)
{
    __shared__ float t[128][65];
    const int b = blockIdx.z, h = blockIdx.y, j0 = blockIdx.x * 128;
    const int tid = threadIdx.x;
#pragma unroll
    for (int i = 0; i < 8; i++) {
        const int idx = tid + i * 256;
        const int row = idx >> 4, c4 = (idx & 15) * 4;
        float4 v = *(const float4*)(x + ((size_t)b * S_ + j0 + row) * D_ + h * 64 + c4);
        t[row][c4 + 0] = wmma::__float_to_tf32(v.x);
        t[row][c4 + 1] = wmma::__float_to_tf32(v.y);
        t[row][c4 + 2] = wmma::__float_to_tf32(v.z);
        t[row][c4 + 3] = wmma::__float_to_tf32(v.w);
    }
    __syncthreads();
    const int d = tid >> 2;
    const int pg = (tid & 3) * 32;
    float* dst = g_v + ((size_t)(b * H_ + h) * DH + d) * S_ + j0 + pg;
#pragma unroll
    for (int u = 0; u < 8; u++) {
        float vv[4];
#pragma unroll
        for (int q = 0; q < 4; q++) {
            const int p = pg + u * 4 + q;          // 0..127
            const int tile = p >> 6, p64 = p & 63;
            const int j = tile * 64 + 8 * (p64 >> 3) + ((p64 & 7) >> 1) + 4 * (p64 & 1);
            vv[q] = t[j][d];
        }
        *(float4*)(dst + u * 4) = make_float4(vv[0], vv[1], vv[2], vv[3]);
    }
}

// ---------------------------------------------------------------------------
// Kernel 1: fused q/k projection, raw tf32 mma, permuted float2 operand loads.
// CTA 128x128, 8 warps (wm = wid&1 m-strip of 64; wn = wid>>1 n-strip of 32).
// K-chunk 32, 2-stage cp.async.  Epilogue scatters tf32 q/k in perm layout.
// ---------------------------------------------------------------------------
#define PJ_LD   40
#define PJ_STGF (2 * 128 * PJ_LD)            // floats per stage = 10240
#define PJ_SMEM (2 * PJ_STGF * 4)            // 81920 B
#define PJ_LDC  132

__global__ __launch_bounds__(256, 2) void proj_kernel(const float* __restrict__ bias)
{
    extern __shared__ float sm[];
    __shared__ float sBias[128];

    const int tid = threadIdx.x;
    const int m0 = blockIdx.y * 128;
    const int n0 = blockIdx.x * 128;
    const int wid = tid >> 5;
    const int lane = tid & 31;
    const int gid = lane >> 2;
    const int tig = lane & 3;
    const int wm = wid & 1;
    const int wn = wid >> 1;

    if (tid < 128) sBias[tid] = bias[n0 + tid];

    float acc[4][4][4];
#pragma unroll
    for (int mi = 0; mi < 4; mi++)
#pragma unroll
        for (int ni = 0; ni < 4; ni++)
#pragma unroll
            for (int r = 0; r < 4; r++) acc[mi][ni][r] = 0.f;

    const uint32_t sbase = smem_u32(sm);

    auto load_stage = [&](int s, int k0) {
        const uint32_t aB = sbase + s * (PJ_STGF * 4);
        const uint32_t bB = aB + 128 * PJ_LD * 4;
#pragma unroll
        for (int i = 0; i < 4; i++) {
            const int idx = tid + i * 256;
            const int row = idx >> 3, c16 = idx & 7;
            CP_ASYNC16(aB + row * (PJ_LD * 4) + c16 * 16,
                       g_xc + (size_t)(m0 + row) * D_ + k0 + c16 * 4);
        }
#pragma unroll
        for (int i = 0; i < 4; i++) {
            const int idx = tid + i * 256;
            const int row = idx >> 3, c16 = idx & 7;
            CP_ASYNC16(bB + row * (PJ_LD * 4) + c16 * 16,
                       g_wc + (size_t)(n0 + row) * D_ + k0 + c16 * 4);
        }
        CP_COMMIT();
    };

    load_stage(0, 0);
    load_stage(1, 32);

    const int NKC = D_ / 32;                 // 32 chunks
    for (int kc = 0; kc < NKC; kc++) {
        if (kc < NKC - 1) CP_WAIT(1); else CP_WAIT(0);
        __syncthreads();

        const float* A  = sm + (kc & 1) * PJ_STGF;
        const float* Bp = A + 128 * PJ_LD;
#pragma unroll
        for (int g = 0; g < 4; g++) {
            uint32_t a[4][4];
#pragma unroll
            for (int mi = 0; mi < 4; mi++) {
                const float* qb = A + (wm * 64 + mi * 16 + gid) * PJ_LD + g * 8 + tig * 2;
                float2 lo = *(const float2*)qb;
                float2 hi = *(const float2*)(qb + 8 * PJ_LD);
                a[mi][0] = __float_as_uint(lo.x);
                a[mi][1] = __float_as_uint(hi.x);
                a[mi][2] = __float_as_uint(lo.y);
                a[mi][3] = __float_as_uint(hi.y);
            }
            uint32_t bf[4][2];
#pragma unroll
            for (int ni = 0; ni < 4; ni++) {
                const float* kb = Bp + (wn * 32 + ni * 8 + gid) * PJ_LD + g * 8 + tig * 2;
                float2 f2 = *(const float2*)kb;
                bf[ni][0] = __float_as_uint(f2.x);
                bf[ni][1] = __float_as_uint(f2.y);
            }
#pragma unroll
            for (int mi = 0; mi < 4; mi++)
#pragma unroll
                for (int ni = 0; ni < 4; ni++)
                    mma16n8k8(acc[mi][ni], a[mi], bf[ni]);
        }
        __syncthreads();
        if (kc + 2 < NKC) load_stage(kc & 1, (kc + 2) * 32);
    }

    // ---- epilogue: acc -> Cs -> permuted tf32 scatter to g_q / g_k ----
    float* Cs = sm;                          // 128 x 132 = 67584 B <= 81920
#pragma unroll
    for (int mi = 0; mi < 4; mi++)
#pragma unroll
        for (int ni = 0; ni < 4; ni++) {
            const int r = wm * 64 + mi * 16 + gid;
            const int c = wn * 32 + ni * 8 + 2 * tig;
            *(float2*)&Cs[r * PJ_LDC + c]       = make_float2(acc[mi][ni][0], acc[mi][ni][1]);
            *(float2*)&Cs[(r + 8) * PJ_LDC + c] = make_float2(acc[mi][ni][2], acc[mi][ni][3]);
        }
    __syncthreads();

    {
        const int r    = tid >> 1;
        const int half = tid & 1;
        const int m = m0 + r;
        const int bb = m >> 11;
        const int s_idx = m & 2047;
        const int hh = n0 >> 7;
        const size_t base = (((size_t)bb * H_ + hh) * S_ + s_idx) * DH + half * 32;
        const float* cr = Cs + r * PJ_LDC;
#pragma unroll
        for (int g = 0; g < 4; g++) {
            const int j0c = half * 64 + g * 16;
            float qv[8], kv[8];
#pragma unroll
            for (int jj = 0; jj < 8; jj++) {
                const int pd = (jj >> 1) + 4 * (jj & 1);   // perm8
                qv[jj] = wmma::__float_to_tf32(cr[j0c + 2*pd]     + sBias[j0c + 2*pd]);
                kv[jj] = wmma::__float_to_tf32(cr[j0c + 2*pd + 1] + sBias[j0c + 2*pd + 1]);
            }
            *(float4*)(g_q + base + g * 8)     = make_float4(qv[0], qv[1], qv[2], qv[3]);
            *(float4*)(g_q + base + g * 8 + 4) = make_float4(qv[4], qv[5], qv[6], qv[7]);
            *(float4*)(g_k + base + g * 8)     = make_float4(kv[0], kv[1], kv[2], kv[3]);
            *(float4*)(g_k + base + g * 8 + 4) = make_float4(kv[4], kv[5], kv[6], kv[7]);
        }
    }
}

// ---------------------------------------------------------------------------
// Kernel 2: ksum[b,h,p] = sum_s k[b,h,s,p]   (perm layout flows through)
// ---------------------------------------------------------------------------
__global__ __launch_bounds__(256) void ksum_kernel()
{
    __shared__ float red[256];
    const int bh = blockIdx.x;
    const int t = threadIdx.x;
    const int d = t & 63;
    const int chunk = t >> 6;
    const float* base = g_k + (size_t)bh * S_ * DH;
    float s = 0.f;
    const int j0 = chunk * (S_ / 4), j1 = j0 + (S_ / 4);
    for (int j = j0; j < j1; j++) s += base[(size_t)j * DH + d];
    red[t] = s;
    __syncthreads();
    if (t < 64)
        g_ksum[bh * DH + t] = red[t] + red[64 + t] + red[128 + t] + red[192 + t];
}

// ---------------------------------------------------------------------------
// Kernel 3: fused attention, register-resident A, permuted float2 loads.
// 512 threads: wm = wid>>1 (m strip of 16), wn = wid&1 (j half of 32).
// smem: qs 128x72, ks 2x64x72, vsT 2x64x72, ps 128x72
// ---------------------------------------------------------------------------
#define AT_LD  72
#define AT_QS_F   (128 * AT_LD)
#define AT_KS_F   (64 * AT_LD)
#define AT_SMEM ((AT_QS_F + 4 * AT_KS_F + 128 * AT_LD) * 4)   // 147456

__global__ __launch_bounds__(512, 1) void attn_kernel(float* __restrict__ out)
{
    extern __shared__ float sm[];
    float* qs  = sm;                          // 128 x 72
    float* ksb = qs + AT_QS_F;                // 2 x 64 x 72
    float* vsb = ksb + 2 * AT_KS_F;           // 2 x 64 x 72 (V^T, j-perm)
    float* ps  = vsb + 2 * AT_KS_F;           // 128 x 72
    __shared__ float sKsum[64];
    __shared__ float sMrow[128];

    const int b  = blockIdx.z;
    const int h  = blockIdx.y;
    const int s0 = blockIdx.x * 128;
    const int tid = threadIdx.x;
    const int wid = tid >> 5;
    const int lane = tid & 31;
    const int gid = lane >> 2;
    const int tig = lane & 3;
    const int wm = wid >> 1;
    const int wn = wid & 1;

    const size_t bh = (size_t)b * H_ + h;
    const float* qg = g_q + bh * S_ * DH;
    const float* kg = g_k + bh * S_ * DH;
    const float* vg = g_v + bh * DH * S_;

    const uint32_t qsB = smem_u32(qs);
    const uint32_t ksB = smem_u32(ksb);
    const uint32_t vsB = smem_u32(vsb);

    auto load_kv = [&](int buf, int j0) {
        const uint32_t kB = ksB + buf * (AT_KS_F * 4);
        const uint32_t vB = vsB + buf * (AT_KS_F * 4);
#pragma unroll
        for (int i = 0; i < 2; i++) {
            const int idx = tid + i * 512;
            const int row = idx >> 4, c16 = idx & 15;
            CP_ASYNC16(kB + row * (AT_LD * 4) + c16 * 16,
                       kg + (size_t)(j0 + row) * DH + c16 * 4);
        }
#pragma unroll
        for (int i = 0; i < 2; i++) {
            const int idx = tid + i * 512;
            const int row = idx >> 4, c16 = idx & 15;   // row = d
            CP_ASYNC16(vB + row * (AT_LD * 4) + c16 * 16,
                       vg + (size_t)row * S_ + j0 + c16 * 4);
        }
    };

    // ---- prologue: Q + K/V tile 0 ----
#pragma unroll
    for (int i = 0; i < 4; i++) {
        const int idx = tid + i * 512;
        const int row = idx >> 4, c16 = idx & 15;
        CP_ASYNC16(qsB + row * (AT_LD * 4) + c16 * 16,
                   qg + (size_t)(s0 + row) * DH + c16 * 4);
    }
    load_kv(0, 0);
    CP_COMMIT();
    if (tid < 64) sKsum[tid] = g_ksum[bh * DH + tid];
    CP_WAIT(0);
    __syncthreads();

    const float SCALE = 0.125f;
    if (tid < 128) {
        float s = 0.f;
        const float* qr = qs + tid * AT_LD;
#pragma unroll
        for (int d = 0; d < DH; d++) s += qr[d] * sKsum[d];
        sMrow[tid] = s * (SCALE / (float)S_);
    }
    __syncthreads();

    const float mr0 = sMrow[wm * 16 + gid];
    const float mr1 = sMrow[wm * 16 + gid + 8];

    float oacc[8][4];
#pragma unroll
    for (int nt = 0; nt < 8; nt++)
#pragma unroll
        for (int r = 0; r < 4; r++) oacc[nt][r] = 0.f;

    const int srcA = (lane & ~3) + (tig >> 1);
    const int srcB = srcA + 2;
    const bool odd = (tig & 1) != 0;

    const int NJT = S_ / 64;                 // 32
    for (int jt = 0; jt < NJT; jt++) {
        const int buf = jt & 1;
        CP_WAIT(0);
        __syncthreads();
        if (jt + 1 < NJT) {
            load_kv(buf ^ 1, (jt + 1) * 64);
            CP_COMMIT();
        }

        const float* kss = ksb + buf * AT_KS_F;
        const float* vss = vsb + buf * AT_KS_F;

        // ---- P = Q K^T : 16m x 32j, permuted float2 operand loads ----
        float d[4][4];
#pragma unroll
        for (int tn = 0; tn < 4; tn++)
#pragma unroll
            for (int r = 0; r < 4; r++) d[tn][r] = 0.f;

#pragma unroll
        for (int g = 0; g < 8; g++) {
            uint32_t a[4];
            const float* qb = qs + (wm * 16 + gid) * AT_LD + g * 8 + tig * 2;
            float2 lo = *(const float2*)qb;
            float2 hi = *(const float2*)(qb + 8 * AT_LD);
            a[0] = __float_as_uint(lo.x);
            a[1] = __float_as_uint(hi.x);
            a[2] = __float_as_uint(lo.y);
            a[3] = __float_as_uint(hi.y);
#pragma unroll
            for (int tn = 0; tn < 4; tn++) {
                const float* kb = kss + (wn * 32 + tn * 8 + gid) * AT_LD + g * 8 + tig * 2;
                float2 f2 = *(const float2*)kb;
                uint32_t bb2[2] = { __float_as_uint(f2.x), __float_as_uint(f2.y) };
                mma16n8k8(d[tn], a, bb2);
            }
        }

        // ---- selu in regs, shuffle acc-layout -> A-operand layout ----
        uint32_t av[4][4];
#pragma unroll
        for (int tn = 0; tn < 4; tn++) {
            const float c0 = selu_f(d[tn][0] * SCALE - mr0);
            const float c1 = selu_f(d[tn][1] * SCALE - mr0);
            const float c2 = selu_f(d[tn][2] * SCALE - mr1);
            const float c3 = selu_f(d[tn][3] * SCALE - mr1);
            float s0 = __shfl_sync(0xffffffffu, c0, srcA);
            float s1 = __shfl_sync(0xffffffffu, c1, srcA);
            const float t0 = odd ? s1 : s0;
            s0 = __shfl_sync(0xffffffffu, c2, srcA);
            s1 = __shfl_sync(0xffffffffu, c3, srcA);
            const float t1 = odd ? s1 : s0;
            s0 = __shfl_sync(0xffffffffu, c0, srcB);
            s1 = __shfl_sync(0xffffffffu, c1, srcB);
            const float t2 = odd ? s1 : s0;
            s0 = __shfl_sync(0xffffffffu, c2, srcB);
            s1 = __shfl_sync(0xffffffffu, c3, srcB);
            const float t3 = odd ? s1 : s0;
            av[tn][0] = __float_as_uint(wmma::__float_to_tf32(t0));
            av[tn][1] = __float_as_uint(wmma::__float_to_tf32(t1));
            av[tn][2] = __float_as_uint(wmma::__float_to_tf32(t2));
            av[tn][3] = __float_as_uint(wmma::__float_to_tf32(t3));
        }

        // ---- partial AV over this warp's 32 j's (V^T, j-perm float2) ----
#pragma unroll
        for (int s = 0; s < 4; s++) {
#pragma unroll
            for (int nt = 0; nt < 8; nt++) {
                const float* vb = vss + (nt * 8 + gid) * AT_LD + wn * 32 + s * 8 + tig * 2;
                float2 f2 = *(const float2*)vb;
                uint32_t bb2[2] = { __float_as_uint(f2.x), __float_as_uint(f2.y) };
                mma16n8k8(oacc[nt], av[s], bb2);
            }
        }
    }

    // ---- reduce partials across wn (2 rounds) into ps ----
    __syncthreads();
    if (wn == 0) {
#pragma unroll
        for (int nt = 0; nt < 8; nt++) {
            *(float2*)(ps + (wm * 16 + gid) * AT_LD + nt * 8 + 2 * tig) =
                make_float2(oacc[nt][0], oacc[nt][1]);
            *(float2*)(ps + (wm * 16 + gid + 8) * AT_LD + nt * 8 + 2 * tig) =
                make_float2(oacc[nt][2], oacc[nt][3]);
        }
    }
    __syncthreads();
    if (wn == 1) {
#pragma unroll
        for (int nt = 0; nt < 8; nt++) {
            float2* p0 = (float2*)(ps + (wm * 16 + gid) * AT_LD + nt * 8 + 2 * tig);
            float2* p1 = (float2*)(ps + (wm * 16 + gid + 8) * AT_LD + nt * 8 + 2 * tig);
            float2 v0 = *p0, v1 = *p1;
            v0.x += oacc[nt][0]; v0.y += oacc[nt][1];
            v1.x += oacc[nt][2]; v1.y += oacc[nt][3];
            *p0 = v0; *p1 = v1;
        }
    }
    __syncthreads();

    // ---- epilogue: ps -> gmem (output dims are real d -- not permuted) ----
    {
        const float OS = 0.022097086912079608f;   // 2048^-0.5
        const int r = tid >> 2;
        const int seg = (tid & 3) * 16;
        const float* pr = ps + r * AT_LD + seg;
        float* dst = out + ((size_t)b * S_ + s0 + r) * D_ + h * DH + seg;
#pragma unroll
        for (int v = 0; v < 4; v++) {
            float4 o4 = make_float4(pr[v*4+0] * OS, pr[v*4+1] * OS,
                                    pr[v*4+2] * OS, pr[v*4+3] * OS);
            *(float4*)(dst + v * 4) = o4;
        }
    }
}

// ---------------------------------------------------------------------------
extern "C" void kernel_launch(void* const* d_in, const int* in_sizes, int n_in,
                              void* d_out, int out_size)
{
    const float* x    = (const float*)d_in[0];
    const float* W    = (const float*)d_in[1];
    const float* bias = (const float*)d_in[2];
    float* out = (float*)d_out;

    cudaFuncSetAttribute(proj_kernel,
                         cudaFuncAttributeMaxDynamicSharedMemorySize, PJ_SMEM);
    cudaFuncSetAttribute(attn_kernel,
                         cudaFuncAttributeMaxDynamicSharedMemorySize, AT_SMEM);

    const int cvt_blocks = (int)((X_BLK + W_BLK + 255) / 256);
    cvt_kernel<<<cvt_blocks, 256>>>(x, W);

    dim3 vg(S_ / 128, H_, B_);                       // (16, 16, 4)
    vtr_kernel<<<vg, 256>>>(x);

    dim3 pg(D_ * 2 / 128, (B_ * S_) / 128);          // (16, 64)
    proj_kernel<<<pg, 256, PJ_SMEM>>>(bias);

    ksum_kernel<<<B_ * H_, 256>>>();

    dim3 ag(S_ / 128, H_, B_);                       // (16, 16, 4)
    attn_kernel<<<ag, 512, AT_SMEM>>>(out);
}

// round 8
// speedup vs baseline: 3.8187x; 1.0517x over previous
#include <cuda_runtime.h>
#include <mma.h>
#include <cstdint>

using namespace nvcuda;

#define B_  4
#define S_  2048
#define D_  1024
#define H_  16
#define DH  64

// Scratch (device globals -- no allocations allowed).
// All k-dims stored PERMUTED: within each 8-block, position p holds
// dim 8g + ((p&7)>>1) + 4*(p&1)  -> fragment pairs (c, c+4) are adjacent.
__device__ float g_q[(size_t)B_*H_*S_*DH];       // perm q
__device__ float g_k[(size_t)B_*H_*S_*DH];       // perm k
__device__ float g_v[(size_t)B_*H_*DH*S_];       // V^T: [bh][d][j-perm]
__device__ float g_xc[(size_t)B_*S_*D_];         // perm tf32 x
__device__ float g_wc[(size_t)2*D_*D_];          // perm tf32 W
__device__ float g_kpart[256*64];                // ksum partials
__device__ float g_ksum[B_*H_*DH];               // perm layout

// ---------------------------------------------------------------------------
// helpers
// ---------------------------------------------------------------------------
__device__ __forceinline__ uint32_t smem_u32(const void* p) {
    uint32_t a;
    asm("{ .reg .u64 t; cvta.to.shared.u64 t, %1; cvt.u32.u64 %0, t; }"
        : "=r"(a) : "l"(p));
    return a;
}
#define CP_ASYNC16(dst, src) \
    asm volatile("cp.async.cg.shared.global [%0], [%1], 16;" :: "r"(dst), "l"(src) : "memory")
#define CP_COMMIT() asm volatile("cp.async.commit_group;" ::: "memory")
#define CP_WAIT(N)  asm volatile("cp.async.wait_group %0;" :: "n"(N) : "memory")

__device__ __forceinline__ void mma16n8k8(float* d, const uint32_t* a, const uint32_t* b)
{
    asm volatile(
        "mma.sync.aligned.m16n8k8.row.col.f32.tf32.tf32.f32 "
        "{%0,%1,%2,%3}, {%4,%5,%6,%7}, {%8,%9}, {%0,%1,%2,%3};"
        : "+f"(d[0]), "+f"(d[1]), "+f"(d[2]), "+f"(d[3])
        : "r"(a[0]), "r"(a[1]), "r"(a[2]), "r"(a[3]), "r"(b[0]), "r"(b[1]));
}

__device__ __forceinline__ float selu_f(float s)
{
    return (s > 0.f) ? 1.0507009873554805f * s
                     : 1.7580993408473766f * (__expf(s) - 1.f);
}

// ---------------------------------------------------------------------------
// Kernel 0: tf32-round + 8-block permute x and W into g_xc / g_wc.
// ---------------------------------------------------------------------------
#define X_BLK ((size_t)B_*S_*D_/8)       // 1048576
#define W_BLK ((size_t)2*D_*D_/8)        // 262144

__global__ __launch_bounds__(256) void cvt_kernel(
    const float* __restrict__ x, const float* __restrict__ W)
{
    const size_t i = (size_t)blockIdx.x * 256 + threadIdx.x;
    const float* src; float* dst;
    if (i < X_BLK)               { src = x + i * 8;            dst = g_xc + i * 8; }
    else if (i < X_BLK + W_BLK)  { src = W + (i - X_BLK) * 8;  dst = g_wc + (i - X_BLK) * 8; }
    else return;
    float4 a = *(const float4*)src;
    float4 b = *(const float4*)(src + 4);
    float4 o1 = make_float4(wmma::__float_to_tf32(a.x), wmma::__float_to_tf32(b.x),
                            wmma::__float_to_tf32(a.y), wmma::__float_to_tf32(b.y));
    float4 o2 = make_float4(wmma::__float_to_tf32(a.z), wmma::__float_to_tf32(b.z),
                            wmma::__float_to_tf32(a.w), wmma::__float_to_tf32(b.w));
    *(float4*)dst = o1;
    *(float4*)(dst + 4) = o2;
}

// ---------------------------------------------------------------------------
// Kernel 0b: V^T with j-permutation: g_v[bh][d][p] = tf32(x[b][j(p)][h*64+d])
// ---------------------------------------------------------------------------
__global__ __launch_bounds__(256) void vtr_kernel(const float* __restrict__ x)
{
    __shared__ float t[128][65];
    const int b = blockIdx.z, h = blockIdx.y, j0 = blockIdx.x * 128;
    const int tid = threadIdx.x;
#pragma unroll
    for (int i = 0; i < 8; i++) {
        const int idx = tid + i * 256;
        const int row = idx >> 4, c4 = (idx & 15) * 4;
        float4 v = *(const float4*)(x + ((size_t)b * S_ + j0 + row) * D_ + h * 64 + c4);
        t[row][c4 + 0] = wmma::__float_to_tf32(v.x);
        t[row][c4 + 1] = wmma::__float_to_tf32(v.y);
        t[row][c4 + 2] = wmma::__float_to_tf32(v.z);
        t[row][c4 + 3] = wmma::__float_to_tf32(v.w);
    }
    __syncthreads();
    const int d = tid >> 2;
    const int pg = (tid & 3) * 32;
    float* dst = g_v + ((size_t)(b * H_ + h) * DH + d) * S_ + j0 + pg;
#pragma unroll
    for (int u = 0; u < 8; u++) {
        float vv[4];
#pragma unroll
        for (int q = 0; q < 4; q++) {
            const int p = pg + u * 4 + q;
            const int tile = p >> 6, p64 = p & 63;
            const int j = tile * 64 + 8 * (p64 >> 3) + ((p64 & 7) >> 1) + 4 * (p64 & 1);
            vv[q] = t[j][d];
        }
        *(float4*)(dst + u * 4) = make_float4(vv[0], vv[1], vv[2], vv[3]);
    }
}

// ---------------------------------------------------------------------------
// Kernel 1: fused q/k projection, raw tf32 mma, permuted float2 operand loads.
// (unchanged from R7 -- passing)
// ---------------------------------------------------------------------------
#define PJ_LD   40
#define PJ_STGF (2 * 128 * PJ_LD)
#define PJ_SMEM (2 * PJ_STGF * 4)            // 81920 B
#define PJ_LDC  132

__global__ __launch_bounds__(256, 2) void proj_kernel(const float* __restrict__ bias)
{
    extern __shared__ float sm[];
    __shared__ float sBias[128];

    const int tid = threadIdx.x;
    const int m0 = blockIdx.y * 128;
    const int n0 = blockIdx.x * 128;
    const int wid = tid >> 5;
    const int lane = tid & 31;
    const int gid = lane >> 2;
    const int tig = lane & 3;
    const int wm = wid & 1;
    const int wn = wid >> 1;

    if (tid < 128) sBias[tid] = bias[n0 + tid];

    float acc[4][4][4];
#pragma unroll
    for (int mi = 0; mi < 4; mi++)
#pragma unroll
        for (int ni = 0; ni < 4; ni++)
#pragma unroll
            for (int r = 0; r < 4; r++) acc[mi][ni][r] = 0.f;

    const uint32_t sbase = smem_u32(sm);

    auto load_stage = [&](int s, int k0) {
        const uint32_t aB = sbase + s * (PJ_STGF * 4);
        const uint32_t bB = aB + 128 * PJ_LD * 4;
#pragma unroll
        for (int i = 0; i < 4; i++) {
            const int idx = tid + i * 256;
            const int row = idx >> 3, c16 = idx & 7;
            CP_ASYNC16(aB + row * (PJ_LD * 4) + c16 * 16,
                       g_xc + (size_t)(m0 + row) * D_ + k0 + c16 * 4);
        }
#pragma unroll
        for (int i = 0; i < 4; i++) {
            const int idx = tid + i * 256;
            const int row = idx >> 3, c16 = idx & 7;
            CP_ASYNC16(bB + row * (PJ_LD * 4) + c16 * 16,
                       g_wc + (size_t)(n0 + row) * D_ + k0 + c16 * 4);
        }
        CP_COMMIT();
    };

    load_stage(0, 0);
    load_stage(1, 32);

    const int NKC = D_ / 32;
    for (int kc = 0; kc < NKC; kc++) {
        if (kc < NKC - 1) CP_WAIT(1); else CP_WAIT(0);
        __syncthreads();

        const float* A  = sm + (kc & 1) * PJ_STGF;
        const float* Bp = A + 128 * PJ_LD;
#pragma unroll
        for (int g = 0; g < 4; g++) {
            uint32_t a[4][4];
#pragma unroll
            for (int mi = 0; mi < 4; mi++) {
                const float* qb = A + (wm * 64 + mi * 16 + gid) * PJ_LD + g * 8 + tig * 2;
                float2 lo = *(const float2*)qb;
                float2 hi = *(const float2*)(qb + 8 * PJ_LD);
                a[mi][0] = __float_as_uint(lo.x);
                a[mi][1] = __float_as_uint(hi.x);
                a[mi][2] = __float_as_uint(lo.y);
                a[mi][3] = __float_as_uint(hi.y);
            }
            uint32_t bf[4][2];
#pragma unroll
            for (int ni = 0; ni < 4; ni++) {
                const float* kb = Bp + (wn * 32 + ni * 8 + gid) * PJ_LD + g * 8 + tig * 2;
                float2 f2 = *(const float2*)kb;
                bf[ni][0] = __float_as_uint(f2.x);
                bf[ni][1] = __float_as_uint(f2.y);
            }
#pragma unroll
            for (int mi = 0; mi < 4; mi++)
#pragma unroll
                for (int ni = 0; ni < 4; ni++)
                    mma16n8k8(acc[mi][ni], a[mi], bf[ni]);
        }
        __syncthreads();
        if (kc + 2 < NKC) load_stage(kc & 1, (kc + 2) * 32);
    }

    float* Cs = sm;
#pragma unroll
    for (int mi = 0; mi < 4; mi++)
#pragma unroll
        for (int ni = 0; ni < 4; ni++) {
            const int r = wm * 64 + mi * 16 + gid;
            const int c = wn * 32 + ni * 8 + 2 * tig;
            *(float2*)&Cs[r * PJ_LDC + c]       = make_float2(acc[mi][ni][0], acc[mi][ni][1]);
            *(float2*)&Cs[(r + 8) * PJ_LDC + c] = make_float2(acc[mi][ni][2], acc[mi][ni][3]);
        }
    __syncthreads();

    {
        const int r    = tid >> 1;
        const int half = tid & 1;
        const int m = m0 + r;
        const int bb = m >> 11;
        const int s_idx = m & 2047;
        const int hh = n0 >> 7;
        const size_t base = (((size_t)bb * H_ + hh) * S_ + s_idx) * DH + half * 32;
        const float* cr = Cs + r * PJ_LDC;
#pragma unroll
        for (int g = 0; g < 4; g++) {
            const int j0c = half * 64 + g * 16;
            float qv[8], kv[8];
#pragma unroll
            for (int jj = 0; jj < 8; jj++) {
                const int pd = (jj >> 1) + 4 * (jj & 1);
                qv[jj] = wmma::__float_to_tf32(cr[j0c + 2*pd]     + sBias[j0c + 2*pd]);
                kv[jj] = wmma::__float_to_tf32(cr[j0c + 2*pd + 1] + sBias[j0c + 2*pd + 1]);
            }
            *(float4*)(g_q + base + g * 8)     = make_float4(qv[0], qv[1], qv[2], qv[3]);
            *(float4*)(g_q + base + g * 8 + 4) = make_float4(qv[4], qv[5], qv[6], qv[7]);
            *(float4*)(g_k + base + g * 8)     = make_float4(kv[0], kv[1], kv[2], kv[3]);
            *(float4*)(g_k + base + g * 8 + 4) = make_float4(kv[4], kv[5], kv[6], kv[7]);
        }
    }
}

// ---------------------------------------------------------------------------
// Kernel 2a/2b: ksum split (256-block partial then reduce)
// ---------------------------------------------------------------------------
__global__ __launch_bounds__(256) void ksum1_kernel()
{
    __shared__ float red[256];
    const int blk = blockIdx.x;              // bh*4 + c
    const int bh = blk >> 2, c = blk & 3;
    const int t = threadIdx.x;
    const int d = t & 63;
    const int sub = t >> 6;                  // 0..3
    const float* base = g_k + (size_t)bh * S_ * DH;
    const int j0 = c * 512 + sub * 128, j1 = j0 + 128;
    float s = 0.f;
    for (int j = j0; j < j1; j++) s += base[(size_t)j * DH + d];
    red[t] = s;
    __syncthreads();
    if (t < 64)
        g_kpart[blk * 64 + t] = red[t] + red[64 + t] + red[128 + t] + red[192 + t];
}

__global__ __launch_bounds__(64) void ksum2_kernel()
{
    const int bh = blockIdx.x;
    const int d = threadIdx.x;
    g_ksum[bh * 64 + d] = g_kpart[(bh * 4 + 0) * 64 + d] + g_kpart[(bh * 4 + 1) * 64 + d]
                        + g_kpart[(bh * 4 + 2) * 64 + d] + g_kpart[(bh * 4 + 3) * 64 + d];
}

// ---------------------------------------------------------------------------
// Kernel 3: fused attention.  K rows placed in smem with perm8 so the P
// accumulator registers ARE the AV A-fragment (no shuffles).
// 512 threads: wm = wid>>1 (m strip of 16), wn = wid&1 (j half of 32).
// smem: qs 128x72, ks 2x64x72 (j-perm rows), vsT 2x64x72 (j-perm), ps 128x72
// ---------------------------------------------------------------------------
#define AT_LD  72
#define AT_QS_F   (128 * AT_LD)
#define AT_KS_F   (64 * AT_LD)
#define AT_SMEM ((AT_QS_F + 4 * AT_KS_F + 128 * AT_LD) * 4)   // 147456

__global__ __launch_bounds__(512, 1) void attn_kernel(float* __restrict__ out)
{
    extern __shared__ float sm[];
    float* qs  = sm;                          // 128 x 72
    float* ksb = qs + AT_QS_F;                // 2 x 64 x 72 (rows j-perm)
    float* vsb = ksb + 2 * AT_KS_F;           // 2 x 64 x 72 (V^T, j-perm)
    float* ps  = vsb + 2 * AT_KS_F;           // 128 x 72
    __shared__ float sKsum[64];
    __shared__ float sMrow[128];

    const int b  = blockIdx.z;
    const int h  = blockIdx.y;
    const int s0 = blockIdx.x * 128;
    const int tid = threadIdx.x;
    const int wid = tid >> 5;
    const int lane = tid & 31;
    const int gid = lane >> 2;
    const int tig = lane & 3;
    const int wm = wid >> 1;
    const int wn = wid & 1;

    const size_t bh = (size_t)b * H_ + h;
    const float* qg = g_q + bh * S_ * DH;
    const float* kg = g_k + bh * S_ * DH;
    const float* vg = g_v + bh * DH * S_;

    const uint32_t qsB = smem_u32(qs);
    const uint32_t ksB = smem_u32(ksb);
    const uint32_t vsB = smem_u32(vsb);

    auto load_kv = [&](int buf, int j0) {
        const uint32_t kB = ksB + buf * (AT_KS_F * 4);
        const uint32_t vB = vsB + buf * (AT_KS_F * 4);
#pragma unroll
        for (int i = 0; i < 2; i++) {
            const int idx = tid + i * 512;
            const int row = idx >> 4, c16 = idx & 15;
            // smem position 'row' holds original j-row jmap(row): perm8
            const int jrow = (row & ~7) + ((row & 7) >> 1) + 4 * (row & 1);
            CP_ASYNC16(kB + row * (AT_LD * 4) + c16 * 16,
                       kg + (size_t)(j0 + jrow) * DH + c16 * 4);
        }
#pragma unroll
        for (int i = 0; i < 2; i++) {
            const int idx = tid + i * 512;
            const int row = idx >> 4, c16 = idx & 15;   // row = d
            CP_ASYNC16(vB + row * (AT_LD * 4) + c16 * 16,
                       vg + (size_t)row * S_ + j0 + c16 * 4);
        }
    };

    // ---- prologue: Q + K/V tile 0 ----
#pragma unroll
    for (int i = 0; i < 4; i++) {
        const int idx = tid + i * 512;
        const int row = idx >> 4, c16 = idx & 15;
        CP_ASYNC16(qsB + row * (AT_LD * 4) + c16 * 16,
                   qg + (size_t)(s0 + row) * DH + c16 * 4);
    }
    load_kv(0, 0);
    CP_COMMIT();
    if (tid < 64) sKsum[tid] = g_ksum[bh * DH + tid];
    CP_WAIT(0);
    __syncthreads();

    const float SCALE = 0.125f;
    if (tid < 128) {
        float s = 0.f;
        const float* qr = qs + tid * AT_LD;
#pragma unroll
        for (int d = 0; d < DH; d++) s += qr[d] * sKsum[d];
        sMrow[tid] = s * (SCALE / (float)S_);
    }
    __syncthreads();

    const float mr0 = sMrow[wm * 16 + gid];
    const float mr1 = sMrow[wm * 16 + gid + 8];

    float oacc[8][4];
#pragma unroll
    for (int nt = 0; nt < 8; nt++)
#pragma unroll
        for (int r = 0; r < 4; r++) oacc[nt][r] = 0.f;

    const int NJT = S_ / 64;                 // 32
    for (int jt = 0; jt < NJT; jt++) {
        const int buf = jt & 1;
        CP_WAIT(0);
        __syncthreads();
        if (jt + 1 < NJT) {
            load_kv(buf ^ 1, (jt + 1) * 64);
            CP_COMMIT();
        }

        const float* kss = ksb + buf * AT_KS_F;
        const float* vss = vsb + buf * AT_KS_F;

        // ---- P = Q K^T : 16m x 32j (cols in perm8 position order) ----
        float d[4][4];
#pragma unroll
        for (int tn = 0; tn < 4; tn++)
#pragma unroll
            for (int r = 0; r < 4; r++) d[tn][r] = 0.f;

#pragma unroll
        for (int g = 0; g < 8; g++) {
            uint32_t a[4];
            const float* qb = qs + (wm * 16 + gid) * AT_LD + g * 8 + tig * 2;
            float2 lo = *(const float2*)qb;
            float2 hi = *(const float2*)(qb + 8 * AT_LD);
            a[0] = __float_as_uint(lo.x);
            a[1] = __float_as_uint(hi.x);
            a[2] = __float_as_uint(lo.y);
            a[3] = __float_as_uint(hi.y);
#pragma unroll
            for (int tn = 0; tn < 4; tn++) {
                const float* kb = kss + (wn * 32 + tn * 8 + gid) * AT_LD + g * 8 + tig * 2;
                float2 f2 = *(const float2*)kb;
                uint32_t bb2[2] = { __float_as_uint(f2.x), __float_as_uint(f2.y) };
                mma16n8k8(d[tn], a, bb2);
            }
        }

        // ---- selu in regs; acc regs ARE the A fragment (reorder only) ----
        uint32_t av[4][4];
#pragma unroll
        for (int tn = 0; tn < 4; tn++) {
            // acc col position 2tig -> j=tig ; 2tig+1 -> j=tig+4  (perm8)
            const float e0 = selu_f(d[tn][0] * SCALE - mr0);   // (gid,   j=tig)
            const float e1 = selu_f(d[tn][1] * SCALE - mr0);   // (gid,   j=tig+4)
            const float e2 = selu_f(d[tn][2] * SCALE - mr1);   // (gid+8, j=tig)
            const float e3 = selu_f(d[tn][3] * SCALE - mr1);   // (gid+8, j=tig+4)
            av[tn][0] = __float_as_uint(wmma::__float_to_tf32(e0));
            av[tn][1] = __float_as_uint(wmma::__float_to_tf32(e2));
            av[tn][2] = __float_as_uint(wmma::__float_to_tf32(e1));
            av[tn][3] = __float_as_uint(wmma::__float_to_tf32(e3));
        }

        // ---- partial AV over this warp's 32 j's (V^T, j-perm float2) ----
#pragma unroll
        for (int s = 0; s < 4; s++) {
#pragma unroll
            for (int nt = 0; nt < 8; nt++) {
                const float* vb = vss + (nt * 8 + gid) * AT_LD + wn * 32 + s * 8 + tig * 2;
                float2 f2 = *(const float2*)vb;
                uint32_t bb2[2] = { __float_as_uint(f2.x), __float_as_uint(f2.y) };
                mma16n8k8(oacc[nt], av[s], bb2);
            }
        }
    }

    // ---- reduce partials across wn (2 rounds) into ps ----
    __syncthreads();
    if (wn == 0) {
#pragma unroll
        for (int nt = 0; nt < 8; nt++) {
            *(float2*)(ps + (wm * 16 + gid) * AT_LD + nt * 8 + 2 * tig) =
                make_float2(oacc[nt][0], oacc[nt][1]);
            *(float2*)(ps + (wm * 16 + gid + 8) * AT_LD + nt * 8 + 2 * tig) =
                make_float2(oacc[nt][2], oacc[nt][3]);
        }
    }
    __syncthreads();
    if (wn == 1) {
#pragma unroll
        for (int nt = 0; nt < 8; nt++) {
            float2* p0 = (float2*)(ps + (wm * 16 + gid) * AT_LD + nt * 8 + 2 * tig);
            float2* p1 = (float2*)(ps + (wm * 16 + gid + 8) * AT_LD + nt * 8 + 2 * tig);
            float2 v0 = *p0, v1 = *p1;
            v0.x += oacc[nt][0]; v0.y += oacc[nt][1];
            v1.x += oacc[nt][2]; v1.y += oacc[nt][3];
            *p0 = v0; *p1 = v1;
        }
    }
    __syncthreads();

    // ---- epilogue: ps -> gmem (output d-dims are real, not permuted) ----
    {
        const float OS = 0.022097086912079608f;   // 2048^-0.5
        const int r = tid >> 2;
        const int seg = (tid & 3) * 16;
        const float* pr = ps + r * AT_LD + seg;
        float* dst = out + ((size_t)b * S_ + s0 + r) * D_ + h * DH + seg;
#pragma unroll
        for (int v = 0; v < 4; v++) {
            float4 o4 = make_float4(pr[v*4+0] * OS, pr[v*4+1] * OS,
                                    pr[v*4+2] * OS, pr[v*4+3] * OS);
            *(float4*)(dst + v * 4) = o4;
        }
    }
}

// ---------------------------------------------------------------------------
extern "C" void kernel_launch(void* const* d_in, const int* in_sizes, int n_in,
                              void* d_out, int out_size)
{
    const float* x    = (const float*)d_in[0];
    const float* W    = (const float*)d_in[1];
    const float* bias = (const float*)d_in[2];
    float* out = (float*)d_out;

    cudaFuncSetAttribute(proj_kernel,
                         cudaFuncAttributeMaxDynamicSharedMemorySize, PJ_SMEM);
    cudaFuncSetAttribute(attn_kernel,
                         cudaFuncAttributeMaxDynamicSharedMemorySize, AT_SMEM);

    const int cvt_blocks = (int)((X_BLK + W_BLK + 255) / 256);
    cvt_kernel<<<cvt_blocks, 256>>>(x, W);

    dim3 vg(S_ / 128, H_, B_);                       // (16, 16, 4)
    vtr_kernel<<<vg, 256>>>(x);

    dim3 pg(D_ * 2 / 128, (B_ * S_) / 128);          // (16, 64)
    proj_kernel<<<pg, 256, PJ_SMEM>>>(bias);

    ksum1_kernel<<<256, 256>>>();
    ksum2_kernel<<<64, 64>>>();

    dim3 ag(S_ / 128, H_, B_);                       // (16, 16, 4)
    attn_kernel<<<ag, 512, AT_SMEM>>>(out);
}

// round 9
// speedup vs baseline: 6.3103x; 1.6525x over previous
#include <cuda_runtime.h>
#include <cuda_fp16.h>
#include <cstdint>

#define B_  4
#define S_  2048
#define D_  1024
#define H_  16
#define DH  64

// Scratch (device globals -- no allocations allowed).
// All k-dims stored with perm16: within each 16-block, memory position
// 4t+r (t=0..3, r=0..3) holds dim 2t + r + (r>=2 ? 6 : 0),
// i.e. pairs ordered (2t,2t+1,2t+8,2t+9) -> one LDS.64 per fragment half-pair.
__device__ __half g_qh[(size_t)B_*H_*S_*DH];     // perm16 q
__device__ __half g_kh[(size_t)B_*H_*S_*DH];     // perm16 k
__device__ __half g_vh[(size_t)B_*H_*DH*S_];     // V^T: [bh][d][j perm16]
__device__ __half g_xh[(size_t)B_*S_*D_];        // perm16 x
__device__ __half g_wh[(size_t)2*D_*D_];         // perm16 W
__device__ float  g_kpart[256*64];
__device__ float  g_ksum[B_*H_*DH];              // perm16 layout

// ---------------------------------------------------------------------------
// helpers
// ---------------------------------------------------------------------------
__device__ __forceinline__ uint32_t smem_u32(const void* p) {
    uint32_t a;
    asm("{ .reg .u64 t; cvta.to.shared.u64 t, %1; cvt.u32.u64 %0, t; }"
        : "=r"(a) : "l"(p));
    return a;
}
#define CP_ASYNC16(dst, src) \
    asm volatile("cp.async.cg.shared.global [%0], [%1], 16;" :: "r"(dst), "l"(src) : "memory")
#define CP_COMMIT() asm volatile("cp.async.commit_group;" ::: "memory")
#define CP_WAIT(N)  asm volatile("cp.async.wait_group %0;" :: "n"(N) : "memory")

// fp16 mma m16n8k16 (row.col), fp32 accum, D += A*B
__device__ __forceinline__ void mma_f16(float* d, const uint32_t* a, const uint32_t* b)
{
    asm volatile(
        "mma.sync.aligned.m16n8k16.row.col.f32.f16.f16.f32 "
        "{%0,%1,%2,%3}, {%4,%5,%6,%7}, {%8,%9}, {%0,%1,%2,%3};"
        : "+f"(d[0]), "+f"(d[1]), "+f"(d[2]), "+f"(d[3])
        : "r"(a[0]), "r"(a[1]), "r"(a[2]), "r"(a[3]), "r"(b[0]), "r"(b[1]));
}

__device__ __forceinline__ float selu_f(float s)
{
    return (s > 0.f) ? 1.0507009873554805f * s
                     : 1.7580993408473766f * (__expf(s) - 1.f);
}

__device__ __forceinline__ uint32_t packh2(float lo, float hi)
{
    __half2 h = __floats2half2_rn(lo, hi);
    return *reinterpret_cast<uint32_t*>(&h);
}

__device__ __forceinline__ int orig16(int r)    // perm16 inverse map
{
    const int t = r >> 2, m = r & 3;
    return 2 * t + m + ((m >= 2) ? 6 : 0);
}

// ---------------------------------------------------------------------------
// Kernel 0: fp16 + perm16 convert x and W
// ---------------------------------------------------------------------------
#define XB16 ((size_t)B_*S_*D_/16)       // 524288
#define WB16 ((size_t)2*D_*D_/16)        // 131072

__global__ __launch_bounds__(256) void cvt_kernel(
    const float* __restrict__ x, const float* __restrict__ W)
{
    const size_t i = (size_t)blockIdx.x * 256 + threadIdx.x;
    const float* src; __half* dst;
    if (i < XB16)              { src = x + i * 16;           dst = g_xh + i * 16; }
    else if (i < XB16 + WB16)  { src = W + (i - XB16) * 16;  dst = g_wh + (i - XB16) * 16; }
    else return;
    float v[16];
#pragma unroll
    for (int q = 0; q < 4; q++) *(float4*)&v[q*4] = *(const float4*)(src + q*4);
    __half h[16];
#pragma unroll
    for (int q = 0; q < 16; q++) h[q] = __float2half(v[orig16(q)]);
    *(uint4*)dst       = *(uint4*)&h[0];
    *(uint4*)(dst + 8) = *(uint4*)&h[8];
}

// ---------------------------------------------------------------------------
// Kernel 0b: V^T fp16 with j-perm16: g_vh[bh][d][p] = x[b][jmap(p)][h*64+d]
// ---------------------------------------------------------------------------
__global__ __launch_bounds__(256) void vtr_kernel(const float* __restrict__ x)
{
    __shared__ float t[128][65];
    const int b = blockIdx.z, h = blockIdx.y, j0 = blockIdx.x * 128;
    const int tid = threadIdx.x;
#pragma unroll
    for (int i = 0; i < 8; i++) {
        const int idx = tid + i * 256;
        const int row = idx >> 4, c4 = (idx & 15) * 4;
        float4 v = *(const float4*)(x + ((size_t)b * S_ + j0 + row) * D_ + h * 64 + c4);
        t[row][c4 + 0] = v.x; t[row][c4 + 1] = v.y;
        t[row][c4 + 2] = v.z; t[row][c4 + 3] = v.w;
    }
    __syncthreads();
    const int d = tid >> 2;
    const int pg = (tid & 3) * 32;
    __half* dst = g_vh + ((size_t)(b * H_ + h) * DH + d) * S_ + j0 + pg;
#pragma unroll
    for (int u = 0; u < 4; u++) {
        __half h8[8];
#pragma unroll
        for (int q = 0; q < 8; q++) {
            const int p = pg + u * 8 + q;
            const int j = (p & ~15) + orig16(p & 15);
            h8[q] = __float2half(t[j][d]);
        }
        *(uint4*)(dst + u * 8) = *(uint4*)h8;
    }
}

// ---------------------------------------------------------------------------
// Kernel 1: fused q/k projection, fp16 m16n8k16.
// CTA 128x128, 8 warps (wm m-strip 64, wn n-strip 32), K-chunk 32, 2-stage.
// ---------------------------------------------------------------------------
#define PJ_LDH   48                          // halves per row (96 B)
#define PJ_MAT_B (128 * 96)                  // 12288 B per matrix per stage
#define PJ_STG_B (2 * PJ_MAT_B)              // 24576 B per stage
#define PJ_SMEM  67584                       // max(pipeline 49152, Cs 128*132*4)
#define PJ_LDC   132

__global__ __launch_bounds__(256, 2) void proj_kernel(const float* __restrict__ bias)
{
    extern __shared__ char smc[];
    float* Cs = (float*)smc;
    __shared__ float sBias[128];

    const int tid = threadIdx.x;
    const int m0 = blockIdx.y * 128;
    const int n0 = blockIdx.x * 128;
    const int wid = tid >> 5;
    const int lane = tid & 31;
    const int gid = lane >> 2;
    const int tig = lane & 3;
    const int wm = wid & 1;
    const int wn = wid >> 1;

    if (tid < 128) sBias[tid] = bias[n0 + tid];

    float acc[4][4][4];
#pragma unroll
    for (int mi = 0; mi < 4; mi++)
#pragma unroll
        for (int ni = 0; ni < 4; ni++)
#pragma unroll
            for (int r = 0; r < 4; r++) acc[mi][ni][r] = 0.f;

    const uint32_t sbase = smem_u32(smc);

    auto load_stage = [&](int s, int k0) {
        const uint32_t aB = sbase + s * PJ_STG_B;
        const uint32_t bB = aB + PJ_MAT_B;
#pragma unroll
        for (int i = 0; i < 2; i++) {
            const int idx = tid + i * 256;           // 0..511
            const int row = idx >> 2, c = idx & 3;
            CP_ASYNC16(aB + row * 96 + c * 16,
                       g_xh + (size_t)(m0 + row) * D_ + k0 + c * 8);
        }
#pragma unroll
        for (int i = 0; i < 2; i++) {
            const int idx = tid + i * 256;
            const int row = idx >> 2, c = idx & 3;
            CP_ASYNC16(bB + row * 96 + c * 16,
                       g_wh + (size_t)(n0 + row) * D_ + k0 + c * 8);
        }
        CP_COMMIT();
    };

    load_stage(0, 0);
    load_stage(1, 32);

    const int NKC = D_ / 32;                 // 32 chunks
    for (int kc = 0; kc < NKC; kc++) {
        if (kc < NKC - 1) CP_WAIT(1); else CP_WAIT(0);
        __syncthreads();

        const __half* A  = (const __half*)(smc + (kc & 1) * PJ_STG_B);
        const __half* Bp = A + 128 * PJ_LDH;
#pragma unroll
        for (int kg = 0; kg < 2; kg++) {
            uint32_t a[4][4];
#pragma unroll
            for (int mi = 0; mi < 4; mi++) {
                const __half* ra = A + (wm * 64 + mi * 16 + gid) * PJ_LDH + kg * 16 + tig * 4;
                uint2 lo = *(const uint2*)ra;
                uint2 hi = *(const uint2*)(ra + 8 * PJ_LDH);
                a[mi][0] = lo.x; a[mi][1] = hi.x; a[mi][2] = lo.y; a[mi][3] = hi.y;
            }
            uint32_t bf[4][2];
#pragma unroll
            for (int ni = 0; ni < 4; ni++) {
                const __half* rb = Bp + (wn * 32 + ni * 8 + gid) * PJ_LDH + kg * 16 + tig * 4;
                uint2 f = *(const uint2*)rb;
                bf[ni][0] = f.x; bf[ni][1] = f.y;
            }
#pragma unroll
            for (int mi = 0; mi < 4; mi++)
#pragma unroll
                for (int ni = 0; ni < 4; ni++)
                    mma_f16(acc[mi][ni], a[mi], bf[ni]);
        }
        __syncthreads();
        if (kc + 2 < NKC) load_stage(kc & 1, (kc + 2) * 32);
    }

    // ---- epilogue: acc -> Cs -> perm16 fp16 scatter to g_qh / g_kh ----
#pragma unroll
    for (int mi = 0; mi < 4; mi++)
#pragma unroll
        for (int ni = 0; ni < 4; ni++) {
            const int r = wm * 64 + mi * 16 + gid;
            const int c = wn * 32 + ni * 8 + 2 * tig;
            *(float2*)&Cs[r * PJ_LDC + c]       = make_float2(acc[mi][ni][0], acc[mi][ni][1]);
            *(float2*)&Cs[(r + 8) * PJ_LDC + c] = make_float2(acc[mi][ni][2], acc[mi][ni][3]);
        }
    __syncthreads();

    {
        const int r    = tid >> 1;
        const int hsel = tid & 1;
        const int m = m0 + r;
        const int bb = m >> 11;
        const int s_idx = m & 2047;
        const int hh = n0 >> 7;
        const size_t base = (((size_t)bb * H_ + hh) * S_ + s_idx) * DH;
        const float* cr = Cs + r * PJ_LDC;
#pragma unroll
        for (int bi = 0; bi < 2; bi++) {
            const int bk = hsel * 2 + bi;        // d-block of 16
            __half qh[16], kh[16];
#pragma unroll
            for (int q = 0; q < 16; q++) {
                const int dorig = bk * 16 + orig16(q);
                qh[q] = __float2half(cr[2 * dorig]     + sBias[2 * dorig]);
                kh[q] = __float2half(cr[2 * dorig + 1] + sBias[2 * dorig + 1]);
            }
            *(uint4*)(g_qh + base + bk * 16)     = *(uint4*)&qh[0];
            *(uint4*)(g_qh + base + bk * 16 + 8) = *(uint4*)&qh[8];
            *(uint4*)(g_kh + base + bk * 16)     = *(uint4*)&kh[0];
            *(uint4*)(g_kh + base + bk * 16 + 8) = *(uint4*)&kh[8];
        }
    }
}

// ---------------------------------------------------------------------------
// Kernel 2a/2b: ksum (perm16 layout flows through)
// ---------------------------------------------------------------------------
__global__ __launch_bounds__(256) void ksum1_kernel()
{
    __shared__ float red[256];
    const int blk = blockIdx.x;
    const int bh = blk >> 2, c = blk & 3;
    const int t = threadIdx.x;
    const int d = t & 63;
    const int sub = t >> 6;
    const __half* base = g_kh + (size_t)bh * S_ * DH;
    const int j0 = c * 512 + sub * 128, j1 = j0 + 128;
    float s = 0.f;
    for (int j = j0; j < j1; j++) s += __half2float(base[(size_t)j * DH + d]);
    red[t] = s;
    __syncthreads();
    if (t < 64)
        g_kpart[blk * 64 + t] = red[t] + red[64 + t] + red[128 + t] + red[192 + t];
}

__global__ __launch_bounds__(64) void ksum2_kernel()
{
    const int bh = blockIdx.x;
    const int d = threadIdx.x;
    g_ksum[bh * 64 + d] = g_kpart[(bh * 4 + 0) * 64 + d] + g_kpart[(bh * 4 + 1) * 64 + d]
                        + g_kpart[(bh * 4 + 2) * 64 + d] + g_kpart[(bh * 4 + 3) * 64 + d];
}

// ---------------------------------------------------------------------------
// Kernel 3: fused attention, fp16 m16n8k16, register-resident A.
// 256 threads, 2 CTAs/SM.  8 warps: wm = wid (16 q-rows each, full j=64).
// Acc->A fragment mapping is direct (classic fp16 flash-attn trick).
// smem bytes: qs 128x80h (20480), ks 2x64x80h (20480), vs 2x64x80h (20480),
//             ps 128x68 f32 (34816)  = 96256
// ---------------------------------------------------------------------------
#define AT_LDH  80
#define AT_QS_B (128 * AT_LDH * 2)           // 20480
#define AT_KS_B (64 * AT_LDH * 2)            // 10240
#define AT_PS_OFF (AT_QS_B + 4 * AT_KS_B)    // 61440
#define AT_SMEM (AT_PS_OFF + 128 * 68 * 4)   // 96256

__global__ __launch_bounds__(256, 2) void attn_kernel(float* __restrict__ out)
{
    extern __shared__ char smc[];
    __half* qs  = (__half*)smc;
    __half* ksb = (__half*)(smc + AT_QS_B);
    __half* vsb = (__half*)(smc + AT_QS_B + 2 * AT_KS_B);
    float*  ps  = (float*)(smc + AT_PS_OFF);
    __shared__ float sKsum[64];
    __shared__ float sMrow[128];

    const int b  = blockIdx.z;
    const int h  = blockIdx.y;
    const int s0 = blockIdx.x * 128;
    const int tid = threadIdx.x;
    const int wid = tid >> 5;
    const int lane = tid & 31;
    const int gid = lane >> 2;
    const int tig = lane & 3;
    const int wm = wid;                      // m strip of 16 (0..7)

    const size_t bh = (size_t)b * H_ + h;
    const __half* qg = g_qh + bh * S_ * DH;
    const __half* kg = g_kh + bh * S_ * DH;
    const __half* vg = g_vh + bh * DH * S_;

    const uint32_t qsB = smem_u32(qs);
    const uint32_t ksB = smem_u32(ksb);
    const uint32_t vsB = smem_u32(vsb);

    auto load_kv = [&](int buf, int j0) {
        const uint32_t kB = ksB + buf * AT_KS_B;
        const uint32_t vB = vsB + buf * AT_KS_B;
#pragma unroll
        for (int i = 0; i < 2; i++) {
            const int idx = tid + i * 256;           // 0..511
            const int row = idx >> 3, c = idx & 7;
            CP_ASYNC16(kB + row * 160 + c * 16,
                       kg + (size_t)(j0 + row) * DH + c * 8);
        }
#pragma unroll
        for (int i = 0; i < 2; i++) {
            const int idx = tid + i * 256;
            const int row = idx >> 3, c = idx & 7;   // row = d
            CP_ASYNC16(vB + row * 160 + c * 16,
                       vg + (size_t)row * S_ + j0 + c * 8);
        }
    };

    // ---- prologue: Q + K/V tile 0 ----
#pragma unroll
    for (int i = 0; i < 4; i++) {
        const int idx = tid + i * 256;               // 0..1023
        const int row = idx >> 3, c = idx & 7;
        CP_ASYNC16(qsB + row * 160 + c * 16,
                   qg + (size_t)(s0 + row) * DH + c * 8);
    }
    load_kv(0, 0);
    CP_COMMIT();
    if (tid < 64) sKsum[tid] = g_ksum[bh * DH + tid];
    CP_WAIT(0);
    __syncthreads();

    const float SCALE = 0.125f;
    if (tid < 128) {
        float s = 0.f;
        const __half* qr = qs + tid * AT_LDH;
#pragma unroll
        for (int d = 0; d < DH; d++) s += __half2float(qr[d]) * sKsum[d];
        sMrow[tid] = s * (SCALE / (float)S_);
    }
    __syncthreads();

    const float mr0 = sMrow[wm * 16 + gid];
    const float mr1 = sMrow[wm * 16 + gid + 8];

    float oacc[8][4];
#pragma unroll
    for (int nt = 0; nt < 8; nt++)
#pragma unroll
        for (int r = 0; r < 4; r++) oacc[nt][r] = 0.f;

    const int NJT = S_ / 64;                 // 32
    for (int jt = 0; jt < NJT; jt++) {
        const int buf = jt & 1;
        CP_WAIT(0);
        __syncthreads();                     // K/V[buf] ready; prior reads of buf^1 done
        if (jt + 1 < NJT) {
            load_kv(buf ^ 1, (jt + 1) * 64);
            CP_COMMIT();
        }

        const __half* kss = ksb + buf * (64 * AT_LDH);
        const __half* vss = vsb + buf * (64 * AT_LDH);

        // ---- P = Q K^T : 16m x 64j ----
        float d[8][4];
#pragma unroll
        for (int tn = 0; tn < 8; tn++)
#pragma unroll
            for (int r = 0; r < 4; r++) d[tn][r] = 0.f;

#pragma unroll
        for (int g = 0; g < 4; g++) {
            const __half* ra = qs + (wm * 16 + gid) * AT_LDH + g * 16 + tig * 4;
            uint2 lo = *(const uint2*)ra;
            uint2 hi = *(const uint2*)(ra + 8 * AT_LDH);
            uint32_t a[4] = { lo.x, hi.x, lo.y, hi.y };
#pragma unroll
            for (int tn = 0; tn < 8; tn++) {
                const __half* rb = kss + (tn * 8 + gid) * AT_LDH + g * 16 + tig * 4;
                uint2 f = *(const uint2*)rb;
                uint32_t bb2[2] = { f.x, f.y };
                mma_f16(d[tn], a, bb2);
            }
        }

        // ---- selu in regs; pack acc pairs directly into AV A-fragments ----
        uint32_t av[4][4];
#pragma unroll
        for (int u = 0; u < 4; u++) {
            const float e00 = selu_f(d[2*u][0]   * SCALE - mr0);
            const float e01 = selu_f(d[2*u][1]   * SCALE - mr0);
            const float e10 = selu_f(d[2*u][2]   * SCALE - mr1);
            const float e11 = selu_f(d[2*u][3]   * SCALE - mr1);
            const float f00 = selu_f(d[2*u+1][0] * SCALE - mr0);
            const float f01 = selu_f(d[2*u+1][1] * SCALE - mr0);
            const float f10 = selu_f(d[2*u+1][2] * SCALE - mr1);
            const float f11 = selu_f(d[2*u+1][3] * SCALE - mr1);
            av[u][0] = packh2(e00, e01);     // row gid,   k 2tig,2tig+1
            av[u][1] = packh2(e10, e11);     // row gid+8, k 2tig,2tig+1
            av[u][2] = packh2(f00, f01);     // row gid,   k 2tig+8,2tig+9
            av[u][3] = packh2(f10, f11);     // row gid+8, k 2tig+8,2tig+9
        }

        // ---- oacc += A @ V  (full j=64, V^T j-perm16 fragments) ----
#pragma unroll
        for (int nt = 0; nt < 8; nt++) {
#pragma unroll
            for (int u = 0; u < 4; u++) {
                const __half* rv = vss + (nt * 8 + gid) * AT_LDH + u * 16 + tig * 4;
                uint2 f = *(const uint2*)rv;
                uint32_t bb2[2] = { f.x, f.y };
                mma_f16(oacc[nt], av[u], bb2);
            }
        }
    }

    // ---- epilogue: oacc -> ps -> coalesced gmem ----
    __syncthreads();
#pragma unroll
    for (int nt = 0; nt < 8; nt++) {
        *(float2*)(ps + (wm * 16 + gid) * 68 + nt * 8 + 2 * tig) =
            make_float2(oacc[nt][0], oacc[nt][1]);
        *(float2*)(ps + (wm * 16 + gid + 8) * 68 + nt * 8 + 2 * tig) =
            make_float2(oacc[nt][2], oacc[nt][3]);
    }
    __syncthreads();
    {
        const float OS = 0.022097086912079608f;   // 2048^-0.5
        const int r = tid >> 1;
        const int seg = (tid & 1) * 32;
        const float* pr = ps + r * 68 + seg;
        float* dst = out + ((size_t)b * S_ + s0 + r) * D_ + h * DH + seg;
#pragma unroll
        for (int v = 0; v < 8; v++) {
            float4 o4 = make_float4(pr[v*4+0] * OS, pr[v*4+1] * OS,
                                    pr[v*4+2] * OS, pr[v*4+3] * OS);
            *(float4*)(dst + v * 4) = o4;
        }
    }
}

// ---------------------------------------------------------------------------
extern "C" void kernel_launch(void* const* d_in, const int* in_sizes, int n_in,
                              void* d_out, int out_size)
{
    const float* x    = (const float*)d_in[0];
    const float* W    = (const float*)d_in[1];
    const float* bias = (const float*)d_in[2];
    float* out = (float*)d_out;

    cudaFuncSetAttribute(proj_kernel,
                         cudaFuncAttributeMaxDynamicSharedMemorySize, PJ_SMEM);
    cudaFuncSetAttribute(attn_kernel,
                         cudaFuncAttributeMaxDynamicSharedMemorySize, AT_SMEM);

    const int cvt_blocks = (int)((XB16 + WB16 + 255) / 256);
    cvt_kernel<<<cvt_blocks, 256>>>(x, W);

    dim3 vg(S_ / 128, H_, B_);                       // (16, 16, 4)
    vtr_kernel<<<vg, 256>>>(x);

    dim3 pg(D_ * 2 / 128, (B_ * S_) / 128);          // (16, 64)
    proj_kernel<<<pg, 256, PJ_SMEM>>>(bias);

    ksum1_kernel<<<256, 256>>>();
    ksum2_kernel<<<64, 64>>>();

    dim3 ag(S_ / 128, H_, B_);                       // (16, 16, 4)
    attn_kernel<<<ag, 256, AT_SMEM>>>(out);
}